// round 2
// baseline (speedup 1.0000x reference)
#include <cuda_runtime.h>
#include <math.h>

// Shapes (fixed by the problem)
#define BATCH 32
#define NTURN 20
#define JTOK  64
#define LSEQ  256
#define DDIM  512
#define NJ    (NTURN * JTOK)      // 1280
#define TWOD  (2 * DDIM)          // 1024
#define MROWS (BATCH * LSEQ)      // 8192

#define NEGV  (-4294967295.0f)    // -2^32 + 1

// Scratch (device globals; no allocation in kernel_launch)
__device__ float g_S[BATCH * LSEQ * NJ];    // sim1 scores -> combined weights (in place)
__device__ float g_F[BATCH * LSEQ * TWOD];  // [mul | sub] features

// ---------------------------------------------------------------------------
// GEMM tile config: 128x128 tile, BK=16, 256 threads, 8x8 per-thread tile
// ---------------------------------------------------------------------------
#define BM 128
#define BN 128
#define BK 16

// ---------------------------------------------------------------------------
// Kernel 1: S[b] = keys[b] (256x512) @ queries[b]^T (1280x512)   [NT gemm]
// ---------------------------------------------------------------------------
__global__ __launch_bounds__(256) void k_gemm1(const float* __restrict__ keys,
                                               const float* __restrict__ queries)
{
    const int b  = blockIdx.z;
    const float* A = keys    + b * LSEQ * DDIM;  // M=256, K=512, lda=512
    const float* B = queries + b * NJ   * DDIM;  // N=1280, K=512, ldb=512
    float*       C = g_S     + (size_t)b * LSEQ * NJ;    // ldc=1280
    const int lda = DDIM, ldb = DDIM, ldc = NJ;
    const int m0 = blockIdx.y * BM;
    const int n0 = blockIdx.x * BN;

    __shared__ float As[BK][BM];
    __shared__ float Bs[BK][BN];

    const int tid  = threadIdx.x;
    const int ty   = tid >> 4;          // 0..15
    const int tx   = tid & 15;          // 0..15
    const int lrow = tid >> 2;          // 0..63
    const int lcol = (tid & 3) << 2;    // 0,4,8,12

    float acc[8][8] = {};

    for (int k0 = 0; k0 < DDIM; k0 += BK) {
        #pragma unroll
        for (int r = 0; r < 2; ++r) {
            float4 v = *(const float4*)(A + (m0 + lrow + r*64) * lda + k0 + lcol);
            As[lcol+0][lrow + r*64] = v.x;
            As[lcol+1][lrow + r*64] = v.y;
            As[lcol+2][lrow + r*64] = v.z;
            As[lcol+3][lrow + r*64] = v.w;
        }
        #pragma unroll
        for (int r = 0; r < 2; ++r) {
            float4 v = *(const float4*)(B + (n0 + lrow + r*64) * ldb + k0 + lcol);
            Bs[lcol+0][lrow + r*64] = v.x;
            Bs[lcol+1][lrow + r*64] = v.y;
            Bs[lcol+2][lrow + r*64] = v.z;
            Bs[lcol+3][lrow + r*64] = v.w;
        }
        __syncthreads();
        #pragma unroll
        for (int kk = 0; kk < BK; ++kk) {
            float a[8], bb[8];
            *(float4*)&a[0]  = *(const float4*)&As[kk][ty*4];
            *(float4*)&a[4]  = *(const float4*)&As[kk][64 + ty*4];
            *(float4*)&bb[0] = *(const float4*)&Bs[kk][tx*4];
            *(float4*)&bb[4] = *(const float4*)&Bs[kk][64 + tx*4];
            #pragma unroll
            for (int i = 0; i < 8; ++i)
                #pragma unroll
                for (int j = 0; j < 8; ++j)
                    acc[i][j] = fmaf(a[i], bb[j], acc[i][j]);
        }
        __syncthreads();
    }

    #pragma unroll
    for (int i = 0; i < 8; ++i) {
        const int m = m0 + ((i < 4) ? (ty*4 + i) : (64 + ty*4 + i - 4));
        float* crow = C + (size_t)m * ldc + n0;
        *(float4*)(crow + tx*4)      = make_float4(acc[i][0], acc[i][1], acc[i][2], acc[i][3]);
        *(float4*)(crow + 64 + tx*4) = make_float4(acc[i][4], acc[i][5], acc[i][6], acc[i][7]);
    }
}

// ---------------------------------------------------------------------------
// Kernel 2: per-(b,i) masked softmax over j, turn softmax over n, combined
//           weights c[n,j] = m * w[n] * p[n,j] written back over g_S.
// ---------------------------------------------------------------------------
__global__ __launch_bounds__(256) void k_softmax(const float* __restrict__ qmask,  // [B,20,64]
                                                 const float* __restrict__ kmask)  // [B,256]
{
    const int row = blockIdx.x;       // b*256 + i
    const int b   = row >> 8;

    __shared__ float buf[NJ];
    __shared__ float qm[NJ];
    __shared__ float sim2[32];
    __shared__ float tvalid[32];
    __shared__ float wn[NTURN];

    const int tid = threadIdx.x;
    float* srow = g_S + (size_t)row * NJ;
    const float* qmrow = qmask + b * NJ;

    for (int j = tid; j < NJ; j += 256) { buf[j] = srow[j]; qm[j] = qmrow[j]; }
    __syncthreads();

    const int wid = tid >> 5, lane = tid & 31;
    for (int n = wid; n < NTURN; n += 8) {
        const int base = n * JTOK;
        float q1 = qm[base + lane],        q2 = qm[base + 32 + lane];
        float s1 = buf[base + lane],       s2 = buf[base + 32 + lane];
        float x1 = (q1 == 0.0f) ? NEGV : s1;
        float x2 = (q2 == 0.0f) ? NEGV : s2;

        float mx = fmaxf(x1, x2);
        #pragma unroll
        for (int o = 16; o; o >>= 1) mx = fmaxf(mx, __shfl_xor_sync(0xFFFFFFFFu, mx, o));

        float e1 = __expf(x1 - mx), e2 = __expf(x2 - mx);
        float es = e1 + e2;
        float qs = q1 + q2;
        float sp = e1 * s1 + e2 * s2;   // numerator of sum p*s_raw
        #pragma unroll
        for (int o = 16; o; o >>= 1) {
            es += __shfl_xor_sync(0xFFFFFFFFu, es, o);
            qs += __shfl_xor_sync(0xFFFFFFFFu, qs, o);
            sp += __shfl_xor_sync(0xFFFFFFFFu, sp, o);
        }
        float inv = 1.0f / es;
        buf[base + lane]      = e1 * inv;
        buf[base + 32 + lane] = e2 * inv;
        if (lane == 0) { sim2[n] = sp * inv; tvalid[n] = qs; }
    }
    __syncthreads();

    if (wid == 0) {
        float v = (lane < NTURN && tvalid[lane] != 0.0f) ? sim2[lane] : NEGV;
        float mx = v;
        #pragma unroll
        for (int o = 16; o; o >>= 1) mx = fmaxf(mx, __shfl_xor_sync(0xFFFFFFFFu, mx, o));
        float e = (lane < NTURN) ? __expf(v - mx) : 0.0f;
        float es = e;
        #pragma unroll
        for (int o = 16; o; o >>= 1) es += __shfl_xor_sync(0xFFFFFFFFu, es, o);
        if (lane < NTURN) wn[lane] = e / es;
    }
    __syncthreads();

    const float m = kmask[row];
    for (int idx = tid; idx < NJ; idx += 256) {
        const int n = idx >> 6;
        srow[idx] = m * wn[n] * buf[idx];
    }
}

// ---------------------------------------------------------------------------
// Kernel 3: keys_attn[b] = C[b] (256x1280) @ queries[b] (1280x512)  [NN gemm]
//           epilogue: F = [attn*keys | (attn-keys)^2]
// ---------------------------------------------------------------------------
__global__ __launch_bounds__(256) void k_gemm2(const float* __restrict__ queries,
                                               const float* __restrict__ keys)
{
    const int b  = blockIdx.z;
    const float* A = g_S     + (size_t)b * LSEQ * NJ;    // M=256, K=1280, lda=1280
    const float* B = queries + (size_t)b * NJ   * DDIM;  // K=1280 x N=512 row-major, ldb=512
    const int lda = NJ, ldb = DDIM;
    const int m0 = blockIdx.y * BM;
    const int n0 = blockIdx.x * BN;

    __shared__ float As[BK][BM];
    __shared__ float Bs[BK][BN];

    const int tid  = threadIdx.x;
    const int ty   = tid >> 4;
    const int tx   = tid & 15;
    const int lrow = tid >> 2;
    const int lcol = (tid & 3) << 2;
    const int bkk  = tid >> 5;          // 0..7
    const int bnc  = (tid & 31) << 2;   // 0..124

    float acc[8][8] = {};

    for (int k0 = 0; k0 < NJ; k0 += BK) {
        #pragma unroll
        for (int r = 0; r < 2; ++r) {
            float4 v = *(const float4*)(A + (size_t)(m0 + lrow + r*64) * lda + k0 + lcol);
            As[lcol+0][lrow + r*64] = v.x;
            As[lcol+1][lrow + r*64] = v.y;
            As[lcol+2][lrow + r*64] = v.z;
            As[lcol+3][lrow + r*64] = v.w;
        }
        #pragma unroll
        for (int r = 0; r < 2; ++r) {
            float4 v = *(const float4*)(B + (size_t)(k0 + bkk + r*8) * ldb + n0 + bnc);
            *(float4*)&Bs[bkk + r*8][bnc] = v;
        }
        __syncthreads();
        #pragma unroll
        for (int kk = 0; kk < BK; ++kk) {
            float a[8], bb[8];
            *(float4*)&a[0]  = *(const float4*)&As[kk][ty*4];
            *(float4*)&a[4]  = *(const float4*)&As[kk][64 + ty*4];
            *(float4*)&bb[0] = *(const float4*)&Bs[kk][tx*4];
            *(float4*)&bb[4] = *(const float4*)&Bs[kk][64 + tx*4];
            #pragma unroll
            for (int i = 0; i < 8; ++i)
                #pragma unroll
                for (int j = 0; j < 8; ++j)
                    acc[i][j] = fmaf(a[i], bb[j], acc[i][j]);
        }
        __syncthreads();
    }

    const float* keyb = keys + (size_t)b * LSEQ * DDIM;
    #pragma unroll
    for (int i = 0; i < 8; ++i) {
        const int m = m0 + ((i < 4) ? (ty*4 + i) : (64 + ty*4 + i - 4));
        const size_t frow = (size_t)(b * LSEQ + m) * TWOD;
        #pragma unroll
        for (int c = 0; c < 2; ++c) {
            const int col = n0 + c*64 + tx*4;
            float4 kv = *(const float4*)(keyb + (size_t)m * DDIM + col);
            float a0 = acc[i][c*4+0], a1 = acc[i][c*4+1], a2 = acc[i][c*4+2], a3 = acc[i][c*4+3];
            float d0 = a0 - kv.x, d1 = a1 - kv.y, d2 = a2 - kv.z, d3 = a3 - kv.w;
            *(float4*)(&g_F[frow + col])        = make_float4(a0*kv.x, a1*kv.y, a2*kv.z, a3*kv.w);
            *(float4*)(&g_F[frow + DDIM + col]) = make_float4(d0*d0, d1*d1, d2*d2, d3*d3);
        }
    }
}

// ---------------------------------------------------------------------------
// Kernel 4: out = relu(F (8192x1024) @ W^T (1024x512) + bias)    [NT gemm]
// ---------------------------------------------------------------------------
__global__ __launch_bounds__(256) void k_gemm3(const float* __restrict__ Wm,    // [512,1024]
                                               const float* __restrict__ bias,  // [512]
                                               float* __restrict__ out)
{
    const float* A = g_F;   // M=8192, K=1024, lda=1024
    const float* B = Wm;    // N=512,  K=1024, ldb=1024
    const int lda = TWOD, ldb = TWOD, ldc = DDIM;
    const int m0 = blockIdx.y * BM;
    const int n0 = blockIdx.x * BN;

    __shared__ float As[BK][BM];
    __shared__ float Bs[BK][BN];

    const int tid  = threadIdx.x;
    const int ty   = tid >> 4;
    const int tx   = tid & 15;
    const int lrow = tid >> 2;
    const int lcol = (tid & 3) << 2;

    float acc[8][8] = {};

    for (int k0 = 0; k0 < TWOD; k0 += BK) {
        #pragma unroll
        for (int r = 0; r < 2; ++r) {
            float4 v = *(const float4*)(A + (size_t)(m0 + lrow + r*64) * lda + k0 + lcol);
            As[lcol+0][lrow + r*64] = v.x;
            As[lcol+1][lrow + r*64] = v.y;
            As[lcol+2][lrow + r*64] = v.z;
            As[lcol+3][lrow + r*64] = v.w;
        }
        #pragma unroll
        for (int r = 0; r < 2; ++r) {
            float4 v = *(const float4*)(B + (size_t)(n0 + lrow + r*64) * ldb + k0 + lcol);
            Bs[lcol+0][lrow + r*64] = v.x;
            Bs[lcol+1][lrow + r*64] = v.y;
            Bs[lcol+2][lrow + r*64] = v.z;
            Bs[lcol+3][lrow + r*64] = v.w;
        }
        __syncthreads();
        #pragma unroll
        for (int kk = 0; kk < BK; ++kk) {
            float a[8], bb[8];
            *(float4*)&a[0]  = *(const float4*)&As[kk][ty*4];
            *(float4*)&a[4]  = *(const float4*)&As[kk][64 + ty*4];
            *(float4*)&bb[0] = *(const float4*)&Bs[kk][tx*4];
            *(float4*)&bb[4] = *(const float4*)&Bs[kk][64 + tx*4];
            #pragma unroll
            for (int i = 0; i < 8; ++i)
                #pragma unroll
                for (int j = 0; j < 8; ++j)
                    acc[i][j] = fmaf(a[i], bb[j], acc[i][j]);
        }
        __syncthreads();
    }

    #pragma unroll
    for (int i = 0; i < 8; ++i) {
        const int m = m0 + ((i < 4) ? (ty*4 + i) : (64 + ty*4 + i - 4));
        float* crow = out + (size_t)m * ldc + n0;
        #pragma unroll
        for (int c = 0; c < 2; ++c) {
            const int col = c*64 + tx*4;
            float4 bv = *(const float4*)(bias + n0 + col);
            float4 v;
            v.x = fmaxf(acc[i][c*4+0] + bv.x, 0.0f);
            v.y = fmaxf(acc[i][c*4+1] + bv.y, 0.0f);
            v.z = fmaxf(acc[i][c*4+2] + bv.z, 0.0f);
            v.w = fmaxf(acc[i][c*4+3] + bv.w, 0.0f);
            *(float4*)(crow + col) = v;
        }
    }
}

// ---------------------------------------------------------------------------
extern "C" void kernel_launch(void* const* d_in, const int* in_sizes, int n_in,
                              void* d_out, int out_size)
{
    const float* queries = (const float*)d_in[0];  // [32,20,64,512]
    const float* keys    = (const float*)d_in[1];  // [32,256,512]
    const float* qmask   = (const float*)d_in[2];  // [32,20,64]
    const float* kmask   = (const float*)d_in[3];  // [32,256]
    const float* Wm      = (const float*)d_in[4];  // [512,1024]
    const float* bias    = (const float*)d_in[5];  // [512]
    float* out = (float*)d_out;                    // [32,256,512]

    k_gemm1<<<dim3(NJ / BN, LSEQ / BM, BATCH), 256>>>(keys, queries);
    k_softmax<<<MROWS, 256>>>(qmask, kmask);
    k_gemm2<<<dim3(DDIM / BN, LSEQ / BM, BATCH), 256>>>(queries, keys);
    k_gemm3<<<dim3(DDIM / BN, MROWS / BM), 256>>>(Wm, bias, out);
}

// round 5
// speedup vs baseline: 1.1620x; 1.1620x over previous
#include <cuda_runtime.h>
#include <cuda_bf16.h>
#include <stdint.h>
#include <math.h>

// Shapes
#define BATCH 32
#define NTURN 20
#define JTOK  64
#define LSEQ  256
#define DDIM  512
#define NJ    1280
#define MROWS 8192
#define NEGV  (-4294967295.0f)

// split-K3 layouts: A-side pattern [hi|hi|lo], B-side pattern [hi|lo|hi]
#define K3_1 1536   // gemm1: K=512  *3
#define K3_2 3840   // gemm2: K=1280 *3
#define K3_3 3072   // gemm3: K=1024 *3

// Device scratch (16B-aligned for vectorized access / cp.async sources)
__device__ __align__(16) __nv_bfloat16 g_Ks[(size_t)BATCH*LSEQ*K3_1];  // keys   A-side [hi|hi|lo]
__device__ __align__(16) __nv_bfloat16 g_Qs[(size_t)BATCH*NJ*K3_1];    // queries B-side NT [hi|lo|hi]
__device__ __align__(16) __nv_bfloat16 g_Qn[(size_t)BATCH*K3_2*DDIM];  // queries B-side NN rows [hi|lo|hi]
__device__ __align__(16) float         g_S [(size_t)BATCH*LSEQ*NJ];    // fp32 scores
__device__ __align__(16) __nv_bfloat16 g_Cs[(size_t)BATCH*LSEQ*K3_2];  // weights A-side [hi|hi|lo]
__device__ __align__(16) __nv_bfloat16 g_Fs[(size_t)MROWS*K3_3];       // features A-side [hi|hi|lo]
__device__ __align__(16) __nv_bfloat16 g_Ws[(size_t)DDIM*K3_3];        // W       B-side [hi|lo|hi]

// ---------------------------------------------------------------------------
// helpers
// ---------------------------------------------------------------------------
__device__ __forceinline__ uint32_t smem_u32(const void* p) {
    uint32_t a;
    asm("{ .reg .u64 t; cvta.to.shared.u64 t, %1; cvt.u32.u64 %0, t; }" : "=r"(a) : "l"(p));
    return a;
}
__device__ __forceinline__ void split_bf(float x, __nv_bfloat16& h, __nv_bfloat16& l) {
    h = __float2bfloat16(x);
    l = __float2bfloat16(x - __bfloat162float(h));
}
__device__ __forceinline__ void cpa16(uint32_t saddr, const void* g) {
    asm volatile("cp.async.cg.shared.global [%0], [%1], 16;" :: "r"(saddr), "l"(g));
}
#define CP_COMMIT() asm volatile("cp.async.commit_group;")
#define CP_WAIT0()  asm volatile("cp.async.wait_group 0;")
#define CP_WAIT1()  asm volatile("cp.async.wait_group 1;")

#define LDSM4(R, ADDR) \
    asm volatile("ldmatrix.sync.aligned.m8n8.x4.shared.b16 {%0,%1,%2,%3}, [%4];" \
        : "=r"((R)[0]), "=r"((R)[1]), "=r"((R)[2]), "=r"((R)[3]) : "r"(ADDR))

#define MMA16816(C, A, B0, B1) \
    asm volatile("mma.sync.aligned.m16n8k16.row.col.f32.bf16.bf16.f32 " \
        "{%0,%1,%2,%3},{%4,%5,%6,%7},{%8,%9},{%0,%1,%2,%3};" \
        : "+f"((C)[0]), "+f"((C)[1]), "+f"((C)[2]), "+f"((C)[3]) \
        : "r"((A)[0]), "r"((A)[1]), "r"((A)[2]), "r"((A)[3]), "r"(B0), "r"(B1))

// smem tiles: pitch 40 bf16 (80B) -> conflict-free ldmatrix, 16B-aligned rows
#define PITCH 40
struct alignas(128) SmemTiles {
    __nv_bfloat16 A[2][128][PITCH];
    __nv_bfloat16 B[2][128][PITCH];
};

// ---------------------------------------------------------------------------
// HMMA mainloop: acc[4][4][4] += A[128 x K3] * B[128 x K3]^T
// A row-major (lda). B: TRB=false -> row-major [N][K3] (ldb=K3);
//                      TRB=true  -> row-major [K3][ldb] (NN), transposed on fill.
// ---------------------------------------------------------------------------
template<bool TRB>
__device__ __forceinline__ void load_tiles(SmemTiles& s, uint32_t sbA, uint32_t sbB,
                                           const __nv_bfloat16* A, int lda,
                                           const __nv_bfloat16* B, int ldb,
                                           int c, int buf)
{
    const int tid = threadIdx.x;
    const int k0 = c * 32;
    #pragma unroll
    for (int i = 0; i < 2; ++i) {
        int id = tid + i * 256;
        int r = id >> 2, cc = id & 3;
        cpa16(sbA + (uint32_t)((buf * 128 + r) * PITCH + cc * 8) * 2,
              A + (size_t)r * lda + k0 + cc * 8);
    }
    if (!TRB) {
        #pragma unroll
        for (int i = 0; i < 2; ++i) {
            int id = tid + i * 256;
            int r = id >> 2, cc = id & 3;
            cpa16(sbB + (uint32_t)((buf * 128 + r) * PITCH + cc * 8) * 2,
                  B + (size_t)r * ldb + k0 + cc * 8);
        }
    } else {
        #pragma unroll
        for (int i = 0; i < 8; ++i) {
            int id = tid + i * 256;
            int k = id >> 6, n2 = id & 63;
            __nv_bfloat162 v = *(const __nv_bfloat162*)(B + (size_t)(k0 + k) * ldb + n2 * 2);
            s.B[buf][n2 * 2][k]     = v.x;
            s.B[buf][n2 * 2 + 1][k] = v.y;
        }
    }
}

__device__ __forceinline__ void hmma_compute(uint32_t sbA, uint32_t sbB, int buf,
                                             int lane, int wm0, int wn0,
                                             float acc[4][4][4])
{
    const int rowoff = lane & 15;
    #pragma unroll
    for (int ks = 0; ks < 2; ++ks) {
        const int coloff = ks * 16 + (lane >> 4) * 8;
        uint32_t a[4][4], b[2][4];
        #pragma unroll
        for (int mt = 0; mt < 4; ++mt)
            LDSM4(a[mt], sbA + (uint32_t)((buf * 128 + wm0 + mt * 16 + rowoff) * PITCH + coloff) * 2);
        #pragma unroll
        for (int np = 0; np < 2; ++np)
            LDSM4(b[np], sbB + (uint32_t)((buf * 128 + wn0 + np * 16 + rowoff) * PITCH + coloff) * 2);
        #pragma unroll
        for (int mt = 0; mt < 4; ++mt)
            #pragma unroll
            for (int nt = 0; nt < 4; ++nt)
                MMA16816(acc[mt][nt], a[mt], b[nt >> 1][nt & 1], b[nt >> 1][2 + (nt & 1)]);
    }
}

template<bool TRB>
__device__ __forceinline__ void hmma_loop(SmemTiles& s,
                                          const __nv_bfloat16* A, int lda,
                                          const __nv_bfloat16* B, int ldb,
                                          int nch, float acc[4][4][4])
{
    const int tid = threadIdx.x;
    const int lane = tid & 31, wid = tid >> 5;
    const int wm0 = (wid >> 2) * 64, wn0 = (wid & 3) * 32;
    const uint32_t sbA = smem_u32(&s.A[0][0][0]);
    const uint32_t sbB = smem_u32(&s.B[0][0][0]);

    load_tiles<TRB>(s, sbA, sbB, A, lda, B, ldb, 0, 0);
    CP_COMMIT();

    for (int c = 0; c < nch; ++c) {
        const int buf = c & 1;
        if (c + 1 < nch) {
            load_tiles<TRB>(s, sbA, sbB, A, lda, B, ldb, c + 1, buf ^ 1);
            CP_COMMIT();
            CP_WAIT1();
        } else {
            CP_WAIT0();
        }
        __syncthreads();
        hmma_compute(sbA, sbB, buf, lane, wm0, wn0, acc);
        __syncthreads();
    }
}

// ---------------------------------------------------------------------------
// Conversion kernels (fp32 -> split bf16 layouts)
// ---------------------------------------------------------------------------
__global__ __launch_bounds__(256) void conv_keys(const float* __restrict__ keys)
{
    size_t t = (size_t)blockIdx.x * 256 + threadIdx.x;
    int d4 = t & 127; size_t rk = t >> 7;
    float4 v = *(const float4*)(keys + rk * 512 + d4 * 4);
    __nv_bfloat16 h[4], l[4];
    split_bf(v.x, h[0], l[0]); split_bf(v.y, h[1], l[1]);
    split_bf(v.z, h[2], l[2]); split_bf(v.w, h[3], l[3]);
    __nv_bfloat162 hh0, hh1, ll0, ll1;
    hh0.x = h[0]; hh0.y = h[1]; hh1.x = h[2]; hh1.y = h[3];
    ll0.x = l[0]; ll0.y = l[1]; ll1.x = l[2]; ll1.y = l[3];
    size_t o = rk * K3_1 + d4 * 4;                       // [hi|hi|lo]
    *(__nv_bfloat162*)(g_Ks + o)        = hh0; *(__nv_bfloat162*)(g_Ks + o + 2)    = hh1;
    *(__nv_bfloat162*)(g_Ks + o + 512)  = hh0; *(__nv_bfloat162*)(g_Ks + o + 514)  = hh1;
    *(__nv_bfloat162*)(g_Ks + o + 1024) = ll0; *(__nv_bfloat162*)(g_Ks + o + 1026) = ll1;
}

__global__ __launch_bounds__(256) void conv_q(const float* __restrict__ q)
{
    size_t t = (size_t)blockIdx.x * 256 + threadIdx.x;
    int d4 = t & 127; size_t rj = t >> 7;
    size_t j = rj % NJ, b = rj / NJ;
    float4 v = *(const float4*)(q + rj * 512 + d4 * 4);
    __nv_bfloat16 h[4], l[4];
    split_bf(v.x, h[0], l[0]); split_bf(v.y, h[1], l[1]);
    split_bf(v.z, h[2], l[2]); split_bf(v.w, h[3], l[3]);
    __nv_bfloat162 hh0, hh1, ll0, ll1;
    hh0.x = h[0]; hh0.y = h[1]; hh1.x = h[2]; hh1.y = h[3];
    ll0.x = l[0]; ll0.y = l[1]; ll1.x = l[2]; ll1.y = l[3];
    // NT layout [hi|lo|hi]
    size_t o = rj * K3_1 + d4 * 4;
    *(__nv_bfloat162*)(g_Qs + o)        = hh0; *(__nv_bfloat162*)(g_Qs + o + 2)    = hh1;
    *(__nv_bfloat162*)(g_Qs + o + 512)  = ll0; *(__nv_bfloat162*)(g_Qs + o + 514)  = ll1;
    *(__nv_bfloat162*)(g_Qs + o + 1024) = hh0; *(__nv_bfloat162*)(g_Qs + o + 1026) = hh1;
    // NN layout: row blocks [hi | lo | hi]
    size_t base = b * (size_t)K3_2 * DDIM;
    size_t oh0 = base + (j)          * DDIM + d4 * 4;
    size_t ol  = base + (NJ + j)     * DDIM + d4 * 4;
    size_t oh1 = base + (2 * NJ + j) * DDIM + d4 * 4;
    *(__nv_bfloat162*)(g_Qn + oh0) = hh0; *(__nv_bfloat162*)(g_Qn + oh0 + 2) = hh1;
    *(__nv_bfloat162*)(g_Qn + ol ) = ll0; *(__nv_bfloat162*)(g_Qn + ol  + 2) = ll1;
    *(__nv_bfloat162*)(g_Qn + oh1) = hh0; *(__nv_bfloat162*)(g_Qn + oh1 + 2) = hh1;
}

__global__ __launch_bounds__(256) void conv_w(const float* __restrict__ Wm)
{
    size_t t = (size_t)blockIdx.x * 256 + threadIdx.x;
    int d4 = t & 255; size_t n = t >> 8;
    float4 v = *(const float4*)(Wm + n * 1024 + d4 * 4);
    __nv_bfloat16 h[4], l[4];
    split_bf(v.x, h[0], l[0]); split_bf(v.y, h[1], l[1]);
    split_bf(v.z, h[2], l[2]); split_bf(v.w, h[3], l[3]);
    __nv_bfloat162 hh0, hh1, ll0, ll1;
    hh0.x = h[0]; hh0.y = h[1]; hh1.x = h[2]; hh1.y = h[3];
    ll0.x = l[0]; ll0.y = l[1]; ll1.x = l[2]; ll1.y = l[3];
    size_t o = n * K3_3 + d4 * 4;                        // [hi|lo|hi]
    *(__nv_bfloat162*)(g_Ws + o)        = hh0; *(__nv_bfloat162*)(g_Ws + o + 2)    = hh1;
    *(__nv_bfloat162*)(g_Ws + o + 1024) = ll0; *(__nv_bfloat162*)(g_Ws + o + 1026) = ll1;
    *(__nv_bfloat162*)(g_Ws + o + 2048) = hh0; *(__nv_bfloat162*)(g_Ws + o + 2050) = hh1;
}

// ---------------------------------------------------------------------------
// GEMM1: scores[b] = keys x queries^T  (M=256, N=1280, K3=1536) -> g_S
// ---------------------------------------------------------------------------
__global__ __launch_bounds__(256) void k_hm1()
{
    __shared__ SmemTiles s;
    const int b = blockIdx.z, m0 = blockIdx.y * 128, n0 = blockIdx.x * 128;
    const __nv_bfloat16* A = g_Ks + ((size_t)b * LSEQ + m0) * K3_1;
    const __nv_bfloat16* B = g_Qs + ((size_t)b * NJ   + n0) * K3_1;
    float acc[4][4][4] = {};
    hmma_loop<false>(s, A, K3_1, B, K3_1, K3_1 / 32, acc);

    const int lane = threadIdx.x & 31, wid = threadIdx.x >> 5;
    const int wm0 = (wid >> 2) * 64, wn0 = (wid & 3) * 32;
    float* C = g_S + (size_t)b * LSEQ * NJ;
    #pragma unroll
    for (int mt = 0; mt < 4; ++mt)
        #pragma unroll
        for (int nt = 0; nt < 4; ++nt)
            #pragma unroll
            for (int rh = 0; rh < 2; ++rh) {
                int m = m0 + wm0 + mt * 16 + (lane >> 2) + rh * 8;
                int n = n0 + wn0 + nt * 8 + (lane & 3) * 2;
                *(float2*)(C + (size_t)m * NJ + n) =
                    make_float2(acc[mt][nt][rh * 2], acc[mt][nt][rh * 2 + 1]);
            }
}

// ---------------------------------------------------------------------------
// Softmax + combined weights -> g_Cs split bf16 ([hi|hi|lo], K3=3840)
// ---------------------------------------------------------------------------
__global__ __launch_bounds__(256) void k_softmax(const float* __restrict__ qmask,
                                                 const float* __restrict__ kmask)
{
    const int row = blockIdx.x;
    const int b   = row >> 8;

    __shared__ float buf[NJ];
    __shared__ float qm[NJ];
    __shared__ float sim2[32];
    __shared__ float tvalid[32];
    __shared__ float wn[NTURN];

    const int tid = threadIdx.x;
    const float* srow = g_S + (size_t)row * NJ;
    const float* qmrow = qmask + b * NJ;

    for (int j = tid; j < NJ; j += 256) { buf[j] = srow[j]; qm[j] = qmrow[j]; }
    __syncthreads();

    const int wid = tid >> 5, lane = tid & 31;
    for (int n = wid; n < NTURN; n += 8) {
        const int base = n * JTOK;
        float q1 = qm[base + lane],  q2 = qm[base + 32 + lane];
        float s1 = buf[base + lane], s2 = buf[base + 32 + lane];
        float x1 = (q1 == 0.0f) ? NEGV : s1;
        float x2 = (q2 == 0.0f) ? NEGV : s2;
        float mx = fmaxf(x1, x2);
        #pragma unroll
        for (int o = 16; o; o >>= 1) mx = fmaxf(mx, __shfl_xor_sync(0xFFFFFFFFu, mx, o));
        float e1 = __expf(x1 - mx), e2 = __expf(x2 - mx);
        float es = e1 + e2, qs = q1 + q2, sp = e1 * s1 + e2 * s2;
        #pragma unroll
        for (int o = 16; o; o >>= 1) {
            es += __shfl_xor_sync(0xFFFFFFFFu, es, o);
            qs += __shfl_xor_sync(0xFFFFFFFFu, qs, o);
            sp += __shfl_xor_sync(0xFFFFFFFFu, sp, o);
        }
        float inv = 1.0f / es;
        buf[base + lane]      = e1 * inv;
        buf[base + 32 + lane] = e2 * inv;
        if (lane == 0) { sim2[n] = sp * inv; tvalid[n] = qs; }
    }
    __syncthreads();

    if (wid == 0) {
        float v = (lane < NTURN && tvalid[lane] != 0.0f) ? sim2[lane] : NEGV;
        float mx = v;
        #pragma unroll
        for (int o = 16; o; o >>= 1) mx = fmaxf(mx, __shfl_xor_sync(0xFFFFFFFFu, mx, o));
        float e = (lane < NTURN) ? __expf(v - mx) : 0.0f;
        float es = e;
        #pragma unroll
        for (int o = 16; o; o >>= 1) es += __shfl_xor_sync(0xFFFFFFFFu, es, o);
        if (lane < NTURN) wn[lane] = e / es;
    }
    __syncthreads();

    const float m = kmask[row];
    __nv_bfloat16* crow = g_Cs + (size_t)row * K3_2;
    for (int idx = tid; idx < NJ; idx += 256) {
        const int n = idx >> 6;
        float c = m * wn[n] * buf[idx];
        __nv_bfloat16 h, l; split_bf(c, h, l);
        crow[idx]          = h;
        crow[NJ + idx]     = h;
        crow[2 * NJ + idx] = l;
    }
}

// ---------------------------------------------------------------------------
// GEMM2: attn[b] = C x queries (M=256, N=512, K3=3840, NN) ->
//        g_Fs = split([attn*keys | (attn-keys)^2])
// ---------------------------------------------------------------------------
__global__ __launch_bounds__(256) void k_hm2(const float* __restrict__ keys)
{
    __shared__ SmemTiles s;
    const int b = blockIdx.z, m0 = blockIdx.y * 128, n0 = blockIdx.x * 128;
    const __nv_bfloat16* A = g_Cs + ((size_t)b * LSEQ + m0) * K3_2;
    const __nv_bfloat16* B = g_Qn + (size_t)b * K3_2 * DDIM + n0;
    float acc[4][4][4] = {};
    hmma_loop<true>(s, A, K3_2, B, DDIM, K3_2 / 32, acc);

    const int lane = threadIdx.x & 31, wid = threadIdx.x >> 5;
    const int wm0 = (wid >> 2) * 64, wn0 = (wid & 3) * 32;
    const float* keyb = keys + (size_t)b * LSEQ * DDIM;
    #pragma unroll
    for (int mt = 0; mt < 4; ++mt)
        #pragma unroll
        for (int nt = 0; nt < 4; ++nt)
            #pragma unroll
            for (int rh = 0; rh < 2; ++rh) {
                int m = m0 + wm0 + mt * 16 + (lane >> 2) + rh * 8;
                int n = n0 + wn0 + nt * 8 + (lane & 3) * 2;
                float a0 = acc[mt][nt][rh * 2], a1 = acc[mt][nt][rh * 2 + 1];
                float2 kv = *(const float2*)(keyb + (size_t)m * DDIM + n);
                float mu0 = a0 * kv.x, mu1 = a1 * kv.y;
                float df0 = a0 - kv.x, df1 = a1 - kv.y;
                float sq0 = df0 * df0, sq1 = df1 * df1;
                size_t rowo = ((size_t)b * LSEQ + m) * K3_3;
                __nv_bfloat16 h0, l0, h1, l1;
                __nv_bfloat162 hp, lp;
                split_bf(mu0, h0, l0); split_bf(mu1, h1, l1);
                hp.x = h0; hp.y = h1; lp.x = l0; lp.y = l1;
                *(__nv_bfloat162*)(g_Fs + rowo + n)        = hp;
                *(__nv_bfloat162*)(g_Fs + rowo + 1024 + n) = hp;
                *(__nv_bfloat162*)(g_Fs + rowo + 2048 + n) = lp;
                split_bf(sq0, h0, l0); split_bf(sq1, h1, l1);
                hp.x = h0; hp.y = h1; lp.x = l0; lp.y = l1;
                *(__nv_bfloat162*)(g_Fs + rowo + 512 + n)  = hp;
                *(__nv_bfloat162*)(g_Fs + rowo + 1536 + n) = hp;
                *(__nv_bfloat162*)(g_Fs + rowo + 2560 + n) = lp;
            }
}

// ---------------------------------------------------------------------------
// GEMM3: out = relu(F x W^T + b)  (M=8192, N=512, K3=3072)
// ---------------------------------------------------------------------------
__global__ __launch_bounds__(256) void k_hm3(const float* __restrict__ bias,
                                             float* __restrict__ out)
{
    __shared__ SmemTiles s;
    const int m0 = blockIdx.y * 128, n0 = blockIdx.x * 128;
    const __nv_bfloat16* A = g_Fs + (size_t)m0 * K3_3;
    const __nv_bfloat16* B = g_Ws + (size_t)n0 * K3_3;
    float acc[4][4][4] = {};
    hmma_loop<false>(s, A, K3_3, B, K3_3, K3_3 / 32, acc);

    const int lane = threadIdx.x & 31, wid = threadIdx.x >> 5;
    const int wm0 = (wid >> 2) * 64, wn0 = (wid & 3) * 32;
    #pragma unroll
    for (int mt = 0; mt < 4; ++mt)
        #pragma unroll
        for (int nt = 0; nt < 4; ++nt)
            #pragma unroll
            for (int rh = 0; rh < 2; ++rh) {
                int m = m0 + wm0 + mt * 16 + (lane >> 2) + rh * 8;
                int n = n0 + wn0 + nt * 8 + (lane & 3) * 2;
                float2 bb = *(const float2*)(bias + n);
                float v0 = fmaxf(acc[mt][nt][rh * 2]     + bb.x, 0.0f);
                float v1 = fmaxf(acc[mt][nt][rh * 2 + 1] + bb.y, 0.0f);
                *(float2*)(out + (size_t)m * DDIM + n) = make_float2(v0, v1);
            }
}

// ---------------------------------------------------------------------------
extern "C" void kernel_launch(void* const* d_in, const int* in_sizes, int n_in,
                              void* d_out, int out_size)
{
    const float* queries = (const float*)d_in[0];  // [32,20,64,512]
    const float* keys    = (const float*)d_in[1];  // [32,256,512]
    const float* qmask   = (const float*)d_in[2];  // [32,20,64]
    const float* kmask   = (const float*)d_in[3];  // [32,256]
    const float* Wm      = (const float*)d_in[4];  // [512,1024]
    const float* bias    = (const float*)d_in[5];  // [512]
    float* out = (float*)d_out;                    // [32,256,512]

    conv_keys<<<4096, 256>>>(keys);
    conv_q   <<<20480, 256>>>(queries);
    conv_w   <<<512, 256>>>(Wm);

    k_hm1<<<dim3(NJ / 128, LSEQ / 128, BATCH), 256>>>();
    k_softmax<<<MROWS, 256>>>(qmask, kmask);
    k_hm2<<<dim3(DDIM / 128, LSEQ / 128, BATCH), 256>>>(keys);
    k_hm3<<<dim3(DDIM / 128, MROWS / 128, 1), 256>>>(bias, out);
}

// round 6
// speedup vs baseline: 1.3102x; 1.1276x over previous
#include <cuda_runtime.h>
#include <cuda_bf16.h>
#include <stdint.h>
#include <math.h>

// Shapes
#define BATCH 32
#define NTURN 20
#define JTOK  64
#define LSEQ  256
#define DDIM  512
#define NJ    1280
#define MROWS 8192
#define NEGV  (-4294967295.0f)

// Compact split scratch (hi/lo pairs; pattern A=[hi,hi,lo], B=[hi,lo,hi] applied at load)
__device__ __align__(16) __nv_bfloat16 g_Khi[(size_t)BATCH*LSEQ*DDIM];
__device__ __align__(16) __nv_bfloat16 g_Klo[(size_t)BATCH*LSEQ*DDIM];
__device__ __align__(16) __nv_bfloat16 g_Qhi[(size_t)BATCH*NJ*DDIM];
__device__ __align__(16) __nv_bfloat16 g_Qlo[(size_t)BATCH*NJ*DDIM];
__device__ __align__(16) float         g_S  [(size_t)BATCH*LSEQ*NJ];
__device__ __align__(16) __nv_bfloat16 g_Chi[(size_t)BATCH*LSEQ*NJ];
__device__ __align__(16) __nv_bfloat16 g_Clo[(size_t)BATCH*LSEQ*NJ];
__device__ __align__(16) __nv_bfloat16 g_Fhi[(size_t)MROWS*1024];
__device__ __align__(16) __nv_bfloat16 g_Flo[(size_t)MROWS*1024];
__device__ __align__(16) __nv_bfloat16 g_Whi[(size_t)DDIM*1024];
__device__ __align__(16) __nv_bfloat16 g_Wlo[(size_t)DDIM*1024];

// ---------------------------------------------------------------------------
// helpers
// ---------------------------------------------------------------------------
__device__ __forceinline__ uint32_t smem_u32(const void* p) {
    uint32_t a;
    asm("{ .reg .u64 t; cvta.to.shared.u64 t, %1; cvt.u32.u64 %0, t; }" : "=r"(a) : "l"(p));
    return a;
}
__device__ __forceinline__ void split_bf(float x, __nv_bfloat16& h, __nv_bfloat16& l) {
    h = __float2bfloat16(x);
    l = __float2bfloat16(x - __bfloat162float(h));
}
__device__ __forceinline__ void cpa16(uint32_t saddr, const void* g) {
    asm volatile("cp.async.cg.shared.global [%0], [%1], 16;" :: "r"(saddr), "l"(g));
}
#define CP_COMMIT() asm volatile("cp.async.commit_group;")
#define CP_WAIT0()  asm volatile("cp.async.wait_group 0;")
#define CP_WAIT1()  asm volatile("cp.async.wait_group 1;")

#define LDSM4(R, ADDR) \
    asm volatile("ldmatrix.sync.aligned.m8n8.x4.shared.b16 {%0,%1,%2,%3}, [%4];" \
        : "=r"((R)[0]), "=r"((R)[1]), "=r"((R)[2]), "=r"((R)[3]) : "r"(ADDR))

#define MMA16816(C, A, B0, B1) \
    asm volatile("mma.sync.aligned.m16n8k16.row.col.f32.bf16.bf16.f32 " \
        "{%0,%1,%2,%3},{%4,%5,%6,%7},{%8,%9},{%0,%1,%2,%3};" \
        : "+f"((C)[0]), "+f"((C)[1]), "+f"((C)[2]), "+f"((C)[3]) \
        : "r"((A)[0]), "r"((A)[1]), "r"((A)[2]), "r"((A)[3]), "r"(B0), "r"(B1))

// smem: 3 stages x (A tile + B tile), each 128 rows x PITCH bf16
#define PITCH 40
#define ATILE (128 * PITCH * 2)           // 10240 B
#define BBASE (3 * ATILE)                 // 30720
#define SMEM_BYTES (6 * ATILE)            // 61440

// pattern selectors (per-chunk operand pointer)
__device__ __forceinline__ const __nv_bfloat16* selA(const __nv_bfloat16* hi, const __nv_bfloat16* lo, int c, int bl) {
    return (c / bl) < 2 ? hi : lo;        // [hi|hi|lo]
}
__device__ __forceinline__ const __nv_bfloat16* selB(const __nv_bfloat16* hi, const __nv_bfloat16* lo, int c, int bl) {
    return (c / bl) == 1 ? lo : hi;       // [hi|lo|hi]
}

// ---------------------------------------------------------------------------
// tile loaders
// ---------------------------------------------------------------------------
template<bool TRB>
__device__ __forceinline__ void load_tiles3(char* smem, uint32_t sb, int stage,
                                            const __nv_bfloat16* A, int lda,
                                            const __nv_bfloat16* B, int ldb, int koff)
{
    const int tid = threadIdx.x;
    const uint32_t sA = sb + stage * ATILE;
    const uint32_t sB = sb + BBASE + stage * ATILE;
    #pragma unroll
    for (int i = 0; i < 2; ++i) {
        int id = tid + i * 256;
        int r = id >> 2, cc = id & 3;
        cpa16(sA + (uint32_t)(r * PITCH + cc * 8) * 2, A + (size_t)r * lda + koff + cc * 8);
    }
    if (!TRB) {
        #pragma unroll
        for (int i = 0; i < 2; ++i) {
            int id = tid + i * 256;
            int r = id >> 2, cc = id & 3;
            cpa16(sB + (uint32_t)(r * PITCH + cc * 8) * 2, B + (size_t)r * ldb + koff + cc * 8);
        }
    } else {
        __nv_bfloat16* bs = (__nv_bfloat16*)(smem + BBASE + stage * ATILE);
        #pragma unroll
        for (int i = 0; i < 8; ++i) {
            int id = tid + i * 256;
            int k = id >> 6, n2 = id & 63;
            __nv_bfloat162 v = *(const __nv_bfloat162*)(B + (size_t)(koff + k) * ldb + n2 * 2);
            bs[(n2 * 2) * PITCH + k]     = v.x;
            bs[(n2 * 2 + 1) * PITCH + k] = v.y;
        }
    }
}

__device__ __forceinline__ void hmma_compute(uint32_t sb, int stage,
                                             int lane, int wm0, int wn0,
                                             float acc[4][4][4])
{
    const uint32_t sA = sb + stage * ATILE;
    const uint32_t sB = sb + BBASE + stage * ATILE;
    const int rowoff = lane & 15;
    #pragma unroll
    for (int ks = 0; ks < 2; ++ks) {
        const int coloff = ks * 16 + (lane >> 4) * 8;
        uint32_t a[4][4], b[2][4];
        #pragma unroll
        for (int mt = 0; mt < 4; ++mt)
            LDSM4(a[mt], sA + (uint32_t)((wm0 + mt * 16 + rowoff) * PITCH + coloff) * 2);
        #pragma unroll
        for (int np = 0; np < 2; ++np)
            LDSM4(b[np], sB + (uint32_t)((wn0 + np * 16 + rowoff) * PITCH + coloff) * 2);
        #pragma unroll
        for (int mt = 0; mt < 4; ++mt)
            #pragma unroll
            for (int nt = 0; nt < 4; ++nt)
                MMA16816(acc[mt][nt], a[mt], b[nt >> 1][nt & 1], b[nt >> 1][2 + (nt & 1)]);
    }
}

// 3-stage pipelined mainloop, one __syncthreads per chunk.
template<bool TRB>
__device__ __forceinline__ void hmma_loop3(char* smem,
                                           const __nv_bfloat16* Ahi, const __nv_bfloat16* Alo, int lda,
                                           const __nv_bfloat16* Bhi, const __nv_bfloat16* Blo, int ldb,
                                           int bl, float acc[4][4][4])
{
    const int tid = threadIdx.x;
    const int lane = tid & 31, wid = tid >> 5;
    const int wm0 = (wid >> 2) * 64, wn0 = (wid & 3) * 32;
    const uint32_t sb = smem_u32(smem);
    const int nch = 3 * bl;

    load_tiles3<TRB>(smem, sb, 0, selA(Ahi, Alo, 0, bl), lda, selB(Bhi, Blo, 0, bl), ldb, 0);
    CP_COMMIT();
    load_tiles3<TRB>(smem, sb, 1, selA(Ahi, Alo, 1, bl), lda, selB(Bhi, Blo, 1, bl), ldb, (1 % bl) * 32);
    CP_COMMIT();

    for (int c = 0; c < nch; ++c) {
        if (c + 1 < nch) { CP_WAIT1(); } else { CP_WAIT0(); }
        __syncthreads();
        if (c + 2 < nch) {
            int cn = c + 2;
            load_tiles3<TRB>(smem, sb, cn % 3, selA(Ahi, Alo, cn, bl), lda,
                             selB(Bhi, Blo, cn, bl), ldb, (cn % bl) * 32);
            CP_COMMIT();
        }
        hmma_compute(sb, c % 3, lane, wm0, wn0, acc);
    }
}

// ---------------------------------------------------------------------------
// Conversion kernels (fp32 -> compact hi/lo bf16)
// ---------------------------------------------------------------------------
__device__ __forceinline__ void split4_store(const float4 v, __nv_bfloat16* hi, __nv_bfloat16* lo, size_t o)
{
    __nv_bfloat16 h[4], l[4];
    split_bf(v.x, h[0], l[0]); split_bf(v.y, h[1], l[1]);
    split_bf(v.z, h[2], l[2]); split_bf(v.w, h[3], l[3]);
    __nv_bfloat162 hh0, hh1, ll0, ll1;
    hh0.x = h[0]; hh0.y = h[1]; hh1.x = h[2]; hh1.y = h[3];
    ll0.x = l[0]; ll0.y = l[1]; ll1.x = l[2]; ll1.y = l[3];
    *(__nv_bfloat162*)(hi + o) = hh0; *(__nv_bfloat162*)(hi + o + 2) = hh1;
    *(__nv_bfloat162*)(lo + o) = ll0; *(__nv_bfloat162*)(lo + o + 2) = ll1;
}

__global__ __launch_bounds__(256) void conv_keys(const float* __restrict__ keys)
{
    size_t t = (size_t)blockIdx.x * 256 + threadIdx.x;       // 32*256*128
    size_t o = t * 4;
    split4_store(*(const float4*)(keys + o), g_Khi, g_Klo, o);
}
__global__ __launch_bounds__(256) void conv_q(const float* __restrict__ q)
{
    size_t t = (size_t)blockIdx.x * 256 + threadIdx.x;       // 32*1280*128
    size_t o = t * 4;
    split4_store(*(const float4*)(q + o), g_Qhi, g_Qlo, o);
}
__global__ __launch_bounds__(256) void conv_w(const float* __restrict__ Wm)
{
    size_t t = (size_t)blockIdx.x * 256 + threadIdx.x;       // 512*256
    size_t o = t * 4;
    split4_store(*(const float4*)(Wm + o), g_Whi, g_Wlo, o);
}

// ---------------------------------------------------------------------------
// GEMM1: scores[b] = keys x queries^T  (M=256, N=1280, Kreal=512) -> g_S
// ---------------------------------------------------------------------------
__global__ __launch_bounds__(256, 2) void k_hm1()
{
    extern __shared__ char smem[];
    const int b = blockIdx.z, m0 = blockIdx.y * 128, n0 = blockIdx.x * 128;
    const __nv_bfloat16* Ah = g_Khi + ((size_t)b * LSEQ + m0) * DDIM;
    const __nv_bfloat16* Al = g_Klo + ((size_t)b * LSEQ + m0) * DDIM;
    const __nv_bfloat16* Bh = g_Qhi + ((size_t)b * NJ + n0) * DDIM;
    const __nv_bfloat16* Bl = g_Qlo + ((size_t)b * NJ + n0) * DDIM;
    float acc[4][4][4] = {};
    hmma_loop3<false>(smem, Ah, Al, DDIM, Bh, Bl, DDIM, DDIM / 32, acc);

    const int lane = threadIdx.x & 31, wid = threadIdx.x >> 5;
    const int wm0 = (wid >> 2) * 64, wn0 = (wid & 3) * 32;
    float* C = g_S + (size_t)b * LSEQ * NJ;
    #pragma unroll
    for (int mt = 0; mt < 4; ++mt)
        #pragma unroll
        for (int nt = 0; nt < 4; ++nt)
            #pragma unroll
            for (int rh = 0; rh < 2; ++rh) {
                int m = m0 + wm0 + mt * 16 + (lane >> 2) + rh * 8;
                int n = n0 + wn0 + nt * 8 + (lane & 3) * 2;
                *(float2*)(C + (size_t)m * NJ + n) =
                    make_float2(acc[mt][nt][rh * 2], acc[mt][nt][rh * 2 + 1]);
            }
}

// ---------------------------------------------------------------------------
// Softmax + combined weights -> g_Chi / g_Clo
// ---------------------------------------------------------------------------
__global__ __launch_bounds__(256) void k_softmax(const float* __restrict__ qmask,
                                                 const float* __restrict__ kmask)
{
    const int row = blockIdx.x;
    const int b   = row >> 8;

    __shared__ float buf[NJ];
    __shared__ float qm[NJ];
    __shared__ float sim2[32];
    __shared__ float tvalid[32];
    __shared__ float wn[NTURN];

    const int tid = threadIdx.x;
    const float* srow = g_S + (size_t)row * NJ;
    const float* qmrow = qmask + b * NJ;

    for (int j = tid; j < NJ; j += 256) { buf[j] = srow[j]; qm[j] = qmrow[j]; }
    __syncthreads();

    const int wid = tid >> 5, lane = tid & 31;
    for (int n = wid; n < NTURN; n += 8) {
        const int base = n * JTOK;
        float q1 = qm[base + lane],  q2 = qm[base + 32 + lane];
        float s1 = buf[base + lane], s2 = buf[base + 32 + lane];
        float x1 = (q1 == 0.0f) ? NEGV : s1;
        float x2 = (q2 == 0.0f) ? NEGV : s2;
        float mx = fmaxf(x1, x2);
        #pragma unroll
        for (int o = 16; o; o >>= 1) mx = fmaxf(mx, __shfl_xor_sync(0xFFFFFFFFu, mx, o));
        float e1 = __expf(x1 - mx), e2 = __expf(x2 - mx);
        float es = e1 + e2, qs = q1 + q2, sp = e1 * s1 + e2 * s2;
        #pragma unroll
        for (int o = 16; o; o >>= 1) {
            es += __shfl_xor_sync(0xFFFFFFFFu, es, o);
            qs += __shfl_xor_sync(0xFFFFFFFFu, qs, o);
            sp += __shfl_xor_sync(0xFFFFFFFFu, sp, o);
        }
        float inv = 1.0f / es;
        buf[base + lane]      = e1 * inv;
        buf[base + 32 + lane] = e2 * inv;
        if (lane == 0) { sim2[n] = sp * inv; tvalid[n] = qs; }
    }
    __syncthreads();

    if (wid == 0) {
        float v = (lane < NTURN && tvalid[lane] != 0.0f) ? sim2[lane] : NEGV;
        float mx = v;
        #pragma unroll
        for (int o = 16; o; o >>= 1) mx = fmaxf(mx, __shfl_xor_sync(0xFFFFFFFFu, mx, o));
        float e = (lane < NTURN) ? __expf(v - mx) : 0.0f;
        float es = e;
        #pragma unroll
        for (int o = 16; o; o >>= 1) es += __shfl_xor_sync(0xFFFFFFFFu, es, o);
        if (lane < NTURN) wn[lane] = e / es;
    }
    __syncthreads();

    const float m = kmask[row];
    for (int idx = tid; idx < NJ; idx += 256) {
        const int n = idx >> 6;
        float c = m * wn[n] * buf[idx];
        __nv_bfloat16 h, l; split_bf(c, h, l);
        g_Chi[(size_t)row * NJ + idx] = h;
        g_Clo[(size_t)row * NJ + idx] = l;
    }
}

// ---------------------------------------------------------------------------
// GEMM2: attn[b] = C x queries (M=256, N=512, Kreal=1280, NN) -> g_Fhi/g_Flo
// ---------------------------------------------------------------------------
__global__ __launch_bounds__(256, 2) void k_hm2(const float* __restrict__ keys)
{
    extern __shared__ char smem[];
    const int b = blockIdx.z, m0 = blockIdx.y * 128, n0 = blockIdx.x * 128;
    const __nv_bfloat16* Ah = g_Chi + ((size_t)b * LSEQ + m0) * NJ;
    const __nv_bfloat16* Al = g_Clo + ((size_t)b * LSEQ + m0) * NJ;
    const __nv_bfloat16* Bh = g_Qhi + (size_t)b * NJ * DDIM + n0;
    const __nv_bfloat16* Bl = g_Qlo + (size_t)b * NJ * DDIM + n0;
    float acc[4][4][4] = {};
    hmma_loop3<true>(smem, Ah, Al, NJ, Bh, Bl, DDIM, NJ / 32, acc);

    const int lane = threadIdx.x & 31, wid = threadIdx.x >> 5;
    const int wm0 = (wid >> 2) * 64, wn0 = (wid & 3) * 32;
    const float* keyb = keys + (size_t)b * LSEQ * DDIM;
    #pragma unroll
    for (int mt = 0; mt < 4; ++mt)
        #pragma unroll
        for (int nt = 0; nt < 4; ++nt)
            #pragma unroll
            for (int rh = 0; rh < 2; ++rh) {
                int m = m0 + wm0 + mt * 16 + (lane >> 2) + rh * 8;
                int n = n0 + wn0 + nt * 8 + (lane & 3) * 2;
                float a0 = acc[mt][nt][rh * 2], a1 = acc[mt][nt][rh * 2 + 1];
                float2 kv = *(const float2*)(keyb + (size_t)m * DDIM + n);
                float mu0 = a0 * kv.x, mu1 = a1 * kv.y;
                float df0 = a0 - kv.x, df1 = a1 - kv.y;
                float sq0 = df0 * df0, sq1 = df1 * df1;
                size_t rowo = ((size_t)b * LSEQ + m) * 1024;
                __nv_bfloat16 h0, l0, h1, l1;
                __nv_bfloat162 hp, lp;
                split_bf(mu0, h0, l0); split_bf(mu1, h1, l1);
                hp.x = h0; hp.y = h1; lp.x = l0; lp.y = l1;
                *(__nv_bfloat162*)(g_Fhi + rowo + n) = hp;
                *(__nv_bfloat162*)(g_Flo + rowo + n) = lp;
                split_bf(sq0, h0, l0); split_bf(sq1, h1, l1);
                hp.x = h0; hp.y = h1; lp.x = l0; lp.y = l1;
                *(__nv_bfloat162*)(g_Fhi + rowo + 512 + n) = hp;
                *(__nv_bfloat162*)(g_Flo + rowo + 512 + n) = lp;
            }
}

// ---------------------------------------------------------------------------
// GEMM3: out = relu(F x W^T + b)  (M=8192, N=512, Kreal=1024)
// ---------------------------------------------------------------------------
__global__ __launch_bounds__(256, 2) void k_hm3(const float* __restrict__ bias,
                                                float* __restrict__ out)
{
    extern __shared__ char smem[];
    const int m0 = blockIdx.y * 128, n0 = blockIdx.x * 128;
    const __nv_bfloat16* Ah = g_Fhi + (size_t)m0 * 1024;
    const __nv_bfloat16* Al = g_Flo + (size_t)m0 * 1024;
    const __nv_bfloat16* Bh = g_Whi + (size_t)n0 * 1024;
    const __nv_bfloat16* Bl = g_Wlo + (size_t)n0 * 1024;
    float acc[4][4][4] = {};
    hmma_loop3<false>(smem, Ah, Al, 1024, Bh, Bl, 1024, 1024 / 32, acc);

    const int lane = threadIdx.x & 31, wid = threadIdx.x >> 5;
    const int wm0 = (wid >> 2) * 64, wn0 = (wid & 3) * 32;
    #pragma unroll
    for (int mt = 0; mt < 4; ++mt)
        #pragma unroll
        for (int nt = 0; nt < 4; ++nt)
            #pragma unroll
            for (int rh = 0; rh < 2; ++rh) {
                int m = m0 + wm0 + mt * 16 + (lane >> 2) + rh * 8;
                int n = n0 + wn0 + nt * 8 + (lane & 3) * 2;
                float2 bb = *(const float2*)(bias + n);
                float v0 = fmaxf(acc[mt][nt][rh * 2]     + bb.x, 0.0f);
                float v1 = fmaxf(acc[mt][nt][rh * 2 + 1] + bb.y, 0.0f);
                *(float2*)(out + (size_t)m * DDIM + n) = make_float2(v0, v1);
            }
}

// ---------------------------------------------------------------------------
extern "C" void kernel_launch(void* const* d_in, const int* in_sizes, int n_in,
                              void* d_out, int out_size)
{
    const float* queries = (const float*)d_in[0];  // [32,20,64,512]
    const float* keys    = (const float*)d_in[1];  // [32,256,512]
    const float* qmask   = (const float*)d_in[2];  // [32,20,64]
    const float* kmask   = (const float*)d_in[3];  // [32,256]
    const float* Wm      = (const float*)d_in[4];  // [512,1024]
    const float* bias    = (const float*)d_in[5];  // [512]
    float* out = (float*)d_out;                    // [32,256,512]

    static int attr_done = 0;
    if (!attr_done) {
        cudaFuncSetAttribute(k_hm1, cudaFuncAttributeMaxDynamicSharedMemorySize, SMEM_BYTES);
        cudaFuncSetAttribute(k_hm2, cudaFuncAttributeMaxDynamicSharedMemorySize, SMEM_BYTES);
        cudaFuncSetAttribute(k_hm3, cudaFuncAttributeMaxDynamicSharedMemorySize, SMEM_BYTES);
        attr_done = 1;
    }

    conv_keys<<<4096, 256>>>(keys);
    conv_q   <<<20480, 256>>>(queries);
    conv_w   <<<512, 256>>>(Wm);

    k_hm1<<<dim3(NJ / 128, LSEQ / 128, BATCH), 256, SMEM_BYTES>>>();
    k_softmax<<<MROWS, 256>>>(qmask, kmask);
    k_hm2<<<dim3(DDIM / 128, LSEQ / 128, BATCH), 256, SMEM_BYTES>>>(keys);
    k_hm3<<<dim3(DDIM / 128, MROWS / 128, 1), 256, SMEM_BYTES>>>(bias, out);
}

// round 8
// speedup vs baseline: 1.7210x; 1.3136x over previous
#include <cuda_runtime.h>
#include <cuda_bf16.h>
#include <stdint.h>
#include <math.h>

// Shapes
#define BATCH 32
#define NTURN 20
#define JTOK  64
#define LSEQ  256
#define DDIM  512
#define NJ    1280
#define MROWS 8192
#define NEGV  (-4294967295.0f)

// Compact split scratch (hi/lo; pattern A=[hi,hi,lo], B=[hi,lo,hi] applied per chunk)
__device__ __align__(16) __nv_bfloat16 g_Khi [(size_t)BATCH*LSEQ*DDIM];
__device__ __align__(16) __nv_bfloat16 g_Klo [(size_t)BATCH*LSEQ*DDIM];
__device__ __align__(16) __nv_bfloat16 g_Qhi [(size_t)BATCH*NJ*DDIM];
__device__ __align__(16) __nv_bfloat16 g_Qlo [(size_t)BATCH*NJ*DDIM];
__device__ __align__(16) __nv_bfloat16 g_Qthi[(size_t)BATCH*DDIM*NJ];   // transposed [b][d][j]
__device__ __align__(16) __nv_bfloat16 g_Qtlo[(size_t)BATCH*DDIM*NJ];
__device__ __align__(16) float         g_S   [(size_t)BATCH*LSEQ*NJ];
__device__ __align__(16) __nv_bfloat16 g_Chi [(size_t)BATCH*LSEQ*NJ];
__device__ __align__(16) __nv_bfloat16 g_Clo [(size_t)BATCH*LSEQ*NJ];
__device__ __align__(16) __nv_bfloat16 g_Fhi [(size_t)MROWS*1024];
__device__ __align__(16) __nv_bfloat16 g_Flo [(size_t)MROWS*1024];
__device__ __align__(16) __nv_bfloat16 g_Whi [(size_t)DDIM*1024];
__device__ __align__(16) __nv_bfloat16 g_Wlo [(size_t)DDIM*1024];

// ---------------------------------------------------------------------------
// helpers
// ---------------------------------------------------------------------------
__device__ __forceinline__ uint32_t smem_u32(const void* p) {
    uint32_t a;
    asm("{ .reg .u64 t; cvta.to.shared.u64 t, %1; cvt.u32.u64 %0, t; }" : "=r"(a) : "l"(p));
    return a;
}
__device__ __forceinline__ void split_bf(float x, __nv_bfloat16& h, __nv_bfloat16& l) {
    h = __float2bfloat16(x);
    l = __float2bfloat16(x - __bfloat162float(h));
}
__device__ __forceinline__ void cpa16(uint32_t saddr, const void* g) {
    asm volatile("cp.async.cg.shared.global [%0], [%1], 16;" :: "r"(saddr), "l"(g));
}
#define CP_COMMIT() asm volatile("cp.async.commit_group;")
#define CP_WAIT0()  asm volatile("cp.async.wait_group 0;")

#define LDSM4(R, ADDR) \
    asm volatile("ldmatrix.sync.aligned.m8n8.x4.shared.b16 {%0,%1,%2,%3}, [%4];" \
        : "=r"((R)[0]), "=r"((R)[1]), "=r"((R)[2]), "=r"((R)[3]) : "r"(ADDR))

#define MMA16816(C, A, B0, B1) \
    asm volatile("mma.sync.aligned.m16n8k16.row.col.f32.bf16.bf16.f32 " \
        "{%0,%1,%2,%3},{%4,%5,%6,%7},{%8,%9},{%0,%1,%2,%3};" \
        : "+f"((C)[0]), "+f"((C)[1]), "+f"((C)[2]), "+f"((C)[3]) \
        : "r"((A)[0]), "r"((A)[1]), "r"((A)[2]), "r"((A)[3]), "r"(B0), "r"(B1))

// smem: 2 stages x (A tile + B tile); tile = 128 rows x 64 K-cols, PITCH 72 bf16
#define PITCH 72
#define ATILE (128 * PITCH * 2)           // 18432 B
#define SMEM_BYTES (4 * ATILE)            // 73728 B

// pattern selectors
__device__ __forceinline__ const __nv_bfloat16* selA(const __nv_bfloat16* hi, const __nv_bfloat16* lo, int c, int bl) {
    return (c / bl) < 2 ? hi : lo;        // [hi|hi|lo]
}
__device__ __forceinline__ const __nv_bfloat16* selB(const __nv_bfloat16* hi, const __nv_bfloat16* lo, int c, int bl) {
    return (c / bl) == 1 ? lo : hi;       // [hi|lo|hi]
}

// ---------------------------------------------------------------------------
// load one K=64 chunk of A and B tiles into stage
// ---------------------------------------------------------------------------
__device__ __forceinline__ void load_tiles(uint32_t sb, int stage,
                                           const __nv_bfloat16* A, int lda,
                                           const __nv_bfloat16* B, int ldb, int koff)
{
    const int tid = threadIdx.x;
    const uint32_t sA = sb + stage * ATILE;
    const uint32_t sB = sb + 2 * ATILE + stage * ATILE;
    #pragma unroll
    for (int i = 0; i < 4; ++i) {
        int id = tid + i * 256;           // 1024 x 16B = 128 rows x 64 cols x 2B
        int r = id >> 3, cc = id & 7;
        cpa16(sA + (uint32_t)(r * PITCH + cc * 8) * 2, A + (size_t)r * lda + koff + cc * 8);
    }
    #pragma unroll
    for (int i = 0; i < 4; ++i) {
        int id = tid + i * 256;
        int r = id >> 3, cc = id & 7;
        cpa16(sB + (uint32_t)(r * PITCH + cc * 8) * 2, B + (size_t)r * ldb + koff + cc * 8);
    }
}

__device__ __forceinline__ void hmma_compute(uint32_t sb, int stage,
                                             int lane, int wm0, int wn0,
                                             float acc[4][4][4])
{
    const uint32_t sA = sb + stage * ATILE;
    const uint32_t sB = sb + 2 * ATILE + stage * ATILE;
    const int rowoff = lane & 15;
    #pragma unroll
    for (int ks = 0; ks < 4; ++ks) {
        const int coloff = ks * 16 + (lane >> 4) * 8;
        uint32_t a[4][4], b[2][4];
        #pragma unroll
        for (int mt = 0; mt < 4; ++mt)
            LDSM4(a[mt], sA + (uint32_t)((wm0 + mt * 16 + rowoff) * PITCH + coloff) * 2);
        #pragma unroll
        for (int np = 0; np < 2; ++np)
            LDSM4(b[np], sB + (uint32_t)((wn0 + np * 16 + rowoff) * PITCH + coloff) * 2);
        #pragma unroll
        for (int mt = 0; mt < 4; ++mt)
            #pragma unroll
            for (int nt = 0; nt < 4; ++nt)
                MMA16816(acc[mt][nt], a[mt], b[nt >> 1][nt & 1], b[nt >> 1][2 + (nt & 1)]);
    }
}

// 2-stage pipelined mainloop, one __syncthreads per K=64 chunk.
// bl = Kreal/64; total chunks = 3*bl (split pattern across blocks).
__device__ __forceinline__ void hmma_loop(char* smem,
                                          const __nv_bfloat16* Ahi, const __nv_bfloat16* Alo, int lda,
                                          const __nv_bfloat16* Bhi, const __nv_bfloat16* Blo, int ldb,
                                          int bl, float acc[4][4][4])
{
    const int tid = threadIdx.x;
    const int lane = tid & 31, wid = tid >> 5;
    const int wm0 = (wid >> 2) * 64, wn0 = (wid & 3) * 32;
    const uint32_t sb = smem_u32(smem);
    const int nch = 3 * bl;

    load_tiles(sb, 0, selA(Ahi, Alo, 0, bl), lda, selB(Bhi, Blo, 0, bl), ldb, 0);
    CP_COMMIT();

    for (int c = 0; c < nch; ++c) {
        CP_WAIT0();
        __syncthreads();          // stage c ready on all threads; compute(c-1) done everywhere
        if (c + 1 < nch) {
            int cn = c + 1;
            load_tiles(sb, cn & 1, selA(Ahi, Alo, cn, bl), lda,
                       selB(Bhi, Blo, cn, bl), ldb, (cn % bl) * 64);
            CP_COMMIT();
        }
        hmma_compute(sb, c & 1, lane, wm0, wn0, acc);
    }
}

// ---------------------------------------------------------------------------
// Conversion kernels (fp32 -> compact hi/lo bf16)
// ---------------------------------------------------------------------------
__device__ __forceinline__ void split4_store(const float4 v, __nv_bfloat16* hi, __nv_bfloat16* lo, size_t o)
{
    __nv_bfloat16 h[4], l[4];
    split_bf(v.x, h[0], l[0]); split_bf(v.y, h[1], l[1]);
    split_bf(v.z, h[2], l[2]); split_bf(v.w, h[3], l[3]);
    __nv_bfloat162 hh0, hh1, ll0, ll1;
    hh0.x = h[0]; hh0.y = h[1]; hh1.x = h[2]; hh1.y = h[3];
    ll0.x = l[0]; ll0.y = l[1]; ll1.x = l[2]; ll1.y = l[3];
    *(__nv_bfloat162*)(hi + o) = hh0; *(__nv_bfloat162*)(hi + o + 2) = hh1;
    *(__nv_bfloat162*)(lo + o) = ll0; *(__nv_bfloat162*)(lo + o + 2) = ll1;
}

__global__ __launch_bounds__(256) void conv_keys(const float* __restrict__ keys)
{
    size_t t = (size_t)blockIdx.x * 256 + threadIdx.x;
    size_t o = t * 4;
    split4_store(*(const float4*)(keys + o), g_Khi, g_Klo, o);
}
__global__ __launch_bounds__(256) void conv_q(const float* __restrict__ q)
{
    size_t t = (size_t)blockIdx.x * 256 + threadIdx.x;
    size_t o = t * 4;
    split4_store(*(const float4*)(q + o), g_Qhi, g_Qlo, o);
}
__global__ __launch_bounds__(256) void conv_w(const float* __restrict__ Wm)
{
    size_t t = (size_t)blockIdx.x * 256 + threadIdx.x;
    size_t o = t * 4;
    split4_store(*(const float4*)(Wm + o), g_Whi, g_Wlo, o);
}

// Transpose+split: q[b][j][d] -> Qt{hi,lo}[b][d][j].  Tile: 64 j x 32 d.
__global__ __launch_bounds__(256) void conv_qt(const float* __restrict__ q)
{
    __shared__ __nv_bfloat16 shh[32][72];
    __shared__ __nv_bfloat16 shl[32][72];
    const int b  = blockIdx.z;
    const int d0 = blockIdx.y * 32;
    const int j0 = blockIdx.x * 64;
    const int t  = threadIdx.x;

    #pragma unroll
    for (int i = 0; i < 2; ++i) {
        int jj = (t >> 3) + i * 32;               // 0..63
        int dd = (t & 7) * 4;                     // 0..28
        float4 v = *(const float4*)(q + ((size_t)b * NJ + j0 + jj) * DDIM + d0 + dd);
        __nv_bfloat16 h, l;
        split_bf(v.x, h, l); shh[dd+0][jj] = h; shl[dd+0][jj] = l;
        split_bf(v.y, h, l); shh[dd+1][jj] = h; shl[dd+1][jj] = l;
        split_bf(v.z, h, l); shh[dd+2][jj] = h; shl[dd+2][jj] = l;
        split_bf(v.w, h, l); shh[dd+3][jj] = h; shl[dd+3][jj] = l;
    }
    __syncthreads();

    const int r  = t >> 3;                        // 0..31 (d row)
    const int pc = t & 7;                         // 8 bf16 = 16B chunk
    size_t o = ((size_t)b * DDIM + d0 + r) * NJ + j0 + pc * 8;
    *(uint4*)(g_Qthi + o) = *(const uint4*)&shh[r][pc * 8];
    *(uint4*)(g_Qtlo + o) = *(const uint4*)&shl[r][pc * 8];
}

// ---------------------------------------------------------------------------
// GEMM1: scores[b] = keys x queries^T  (M=256, N=1280, Kreal=512) -> g_S
// ---------------------------------------------------------------------------
__global__ __launch_bounds__(256, 2) void k_hm1()
{
    extern __shared__ char smem[];
    const int b = blockIdx.z, m0 = blockIdx.y * 128, n0 = blockIdx.x * 128;
    const __nv_bfloat16* Ah = g_Khi + ((size_t)b * LSEQ + m0) * DDIM;
    const __nv_bfloat16* Al = g_Klo + ((size_t)b * LSEQ + m0) * DDIM;
    const __nv_bfloat16* Bh = g_Qhi + ((size_t)b * NJ + n0) * DDIM;
    const __nv_bfloat16* Bl = g_Qlo + ((size_t)b * NJ + n0) * DDIM;
    float acc[4][4][4] = {};
    hmma_loop(smem, Ah, Al, DDIM, Bh, Bl, DDIM, DDIM / 64, acc);

    const int lane = threadIdx.x & 31, wid = threadIdx.x >> 5;
    const int wm0 = (wid >> 2) * 64, wn0 = (wid & 3) * 32;
    float* C = g_S + (size_t)b * LSEQ * NJ;
    #pragma unroll
    for (int mt = 0; mt < 4; ++mt)
        #pragma unroll
        for (int nt = 0; nt < 4; ++nt)
            #pragma unroll
            for (int rh = 0; rh < 2; ++rh) {
                int m = m0 + wm0 + mt * 16 + (lane >> 2) + rh * 8;
                int n = n0 + wn0 + nt * 8 + (lane & 3) * 2;
                *(float2*)(C + (size_t)m * NJ + n) =
                    make_float2(acc[mt][nt][rh * 2], acc[mt][nt][rh * 2 + 1]);
            }
}

// ---------------------------------------------------------------------------
// Softmax + combined weights -> g_Chi / g_Clo
// ---------------------------------------------------------------------------
__global__ __launch_bounds__(256) void k_softmax(const float* __restrict__ qmask,
                                                 const float* __restrict__ kmask)
{
    const int row = blockIdx.x;
    const int b   = row >> 8;

    __shared__ float buf[NJ];
    __shared__ float qm[NJ];
    __shared__ float sim2[32];
    __shared__ float tvalid[32];
    __shared__ float wn[NTURN];

    const int tid = threadIdx.x;
    const float* srow = g_S + (size_t)row * NJ;
    const float* qmrow = qmask + b * NJ;

    for (int j = tid; j < NJ; j += 256) { buf[j] = srow[j]; qm[j] = qmrow[j]; }
    __syncthreads();

    const int wid = tid >> 5, lane = tid & 31;
    for (int n = wid; n < NTURN; n += 8) {
        const int base = n * JTOK;
        float q1 = qm[base + lane],  q2 = qm[base + 32 + lane];
        float s1 = buf[base + lane], s2 = buf[base + 32 + lane];
        float x1 = (q1 == 0.0f) ? NEGV : s1;
        float x2 = (q2 == 0.0f) ? NEGV : s2;
        float mx = fmaxf(x1, x2);
        #pragma unroll
        for (int o = 16; o; o >>= 1) mx = fmaxf(mx, __shfl_xor_sync(0xFFFFFFFFu, mx, o));
        float e1 = __expf(x1 - mx), e2 = __expf(x2 - mx);
        float es = e1 + e2, qs = q1 + q2, sp = e1 * s1 + e2 * s2;
        #pragma unroll
        for (int o = 16; o; o >>= 1) {
            es += __shfl_xor_sync(0xFFFFFFFFu, es, o);
            qs += __shfl_xor_sync(0xFFFFFFFFu, qs, o);
            sp += __shfl_xor_sync(0xFFFFFFFFu, sp, o);
        }
        float inv = 1.0f / es;
        buf[base + lane]      = e1 * inv;
        buf[base + 32 + lane] = e2 * inv;
        if (lane == 0) { sim2[n] = sp * inv; tvalid[n] = qs; }
    }
    __syncthreads();

    if (wid == 0) {
        float v = (lane < NTURN && tvalid[lane] != 0.0f) ? sim2[lane] : NEGV;
        float mx = v;
        #pragma unroll
        for (int o = 16; o; o >>= 1) mx = fmaxf(mx, __shfl_xor_sync(0xFFFFFFFFu, mx, o));
        float e = (lane < NTURN) ? __expf(v - mx) : 0.0f;
        float es = e;
        #pragma unroll
        for (int o = 16; o; o >>= 1) es += __shfl_xor_sync(0xFFFFFFFFu, es, o);
        if (lane < NTURN) wn[lane] = e / es;
    }
    __syncthreads();

    const float m = kmask[row];
    for (int idx = tid; idx < NJ; idx += 256) {
        const int n = idx >> 6;
        float c = m * wn[n] * buf[idx];
        __nv_bfloat16 h, l; split_bf(c, h, l);
        g_Chi[(size_t)row * NJ + idx] = h;
        g_Clo[(size_t)row * NJ + idx] = l;
    }
}

// ---------------------------------------------------------------------------
// GEMM2: attn[b] = C x queries (M=256, N=512, Kreal=1280) -> g_Fhi/g_Flo
// B side uses pre-transposed Qt[d][j] (K-major) -> plain cp.async loads.
// ---------------------------------------------------------------------------
__global__ __launch_bounds__(256, 2) void k_hm2(const float* __restrict__ keys)
{
    extern __shared__ char smem[];
    const int b = blockIdx.z, m0 = blockIdx.y * 128, n0 = blockIdx.x * 128;
    const __nv_bfloat16* Ah = g_Chi  + ((size_t)b * LSEQ + m0) * NJ;
    const __nv_bfloat16* Al = g_Clo  + ((size_t)b * LSEQ + m0) * NJ;
    const __nv_bfloat16* Bh = g_Qthi + ((size_t)b * DDIM + n0) * NJ;
    const __nv_bfloat16* Bl = g_Qtlo + ((size_t)b * DDIM + n0) * NJ;
    float acc[4][4][4] = {};
    hmma_loop(smem, Ah, Al, NJ, Bh, Bl, NJ, NJ / 64, acc);

    const int lane = threadIdx.x & 31, wid = threadIdx.x >> 5;
    const int wm0 = (wid >> 2) * 64, wn0 = (wid & 3) * 32;
    const float* keyb = keys + (size_t)b * LSEQ * DDIM;
    #pragma unroll
    for (int mt = 0; mt < 4; ++mt)
        #pragma unroll
        for (int nt = 0; nt < 4; ++nt)
            #pragma unroll
            for (int rh = 0; rh < 2; ++rh) {
                int m = m0 + wm0 + mt * 16 + (lane >> 2) + rh * 8;
                int n = n0 + wn0 + nt * 8 + (lane & 3) * 2;
                float a0 = acc[mt][nt][rh * 2], a1 = acc[mt][nt][rh * 2 + 1];
                float2 kv = *(const float2*)(keyb + (size_t)m * DDIM + n);
                float mu0 = a0 * kv.x, mu1 = a1 * kv.y;
                float df0 = a0 - kv.x, df1 = a1 - kv.y;
                float sq0 = df0 * df0, sq1 = df1 * df1;
                size_t rowo = ((size_t)b * LSEQ + m) * 1024;
                __nv_bfloat16 h0, l0, h1, l1;
                __nv_bfloat162 hp, lp;
                split_bf(mu0, h0, l0); split_bf(mu1, h1, l1);
                hp.x = h0; hp.y = h1; lp.x = l0; lp.y = l1;
                *(__nv_bfloat162*)(g_Fhi + rowo + n) = hp;
                *(__nv_bfloat162*)(g_Flo + rowo + n) = lp;
                split_bf(sq0, h0, l0); split_bf(sq1, h1, l1);
                hp.x = h0; hp.y = h1; lp.x = l0; lp.y = l1;
                *(__nv_bfloat162*)(g_Fhi + rowo + 512 + n) = hp;
                *(__nv_bfloat162*)(g_Flo + rowo + 512 + n) = lp;
            }
}

// ---------------------------------------------------------------------------
// GEMM3: out = relu(F x W^T + b)  (M=8192, N=512, Kreal=1024)
// ---------------------------------------------------------------------------
__global__ __launch_bounds__(256, 2) void k_hm3(const float* __restrict__ bias,
                                                float* __restrict__ out)
{
    extern __shared__ char smem[];
    const int m0 = blockIdx.y * 128, n0 = blockIdx.x * 128;
    const __nv_bfloat16* Ah = g_Fhi + (size_t)m0 * 1024;
    const __nv_bfloat16* Al = g_Flo + (size_t)m0 * 1024;
    const __nv_bfloat16* Bh = g_Whi + (size_t)n0 * 1024;
    const __nv_bfloat16* Bl = g_Wlo + (size_t)n0 * 1024;
    float acc[4][4][4] = {};
    hmma_loop(smem, Ah, Al, 1024, Bh, Bl, 1024, 1024 / 64, acc);

    const int lane = threadIdx.x & 31, wid = threadIdx.x >> 5;
    const int wm0 = (wid >> 2) * 64, wn0 = (wid & 3) * 32;
    #pragma unroll
    for (int mt = 0; mt < 4; ++mt)
        #pragma unroll
        for (int nt = 0; nt < 4; ++nt)
            #pragma unroll
            for (int rh = 0; rh < 2; ++rh) {
                int m = m0 + wm0 + mt * 16 + (lane >> 2) + rh * 8;
                int n = n0 + wn0 + nt * 8 + (lane & 3) * 2;
                float2 bb = *(const float2*)(bias + n);
                float v0 = fmaxf(acc[mt][nt][rh * 2]     + bb.x, 0.0f);
                float v1 = fmaxf(acc[mt][nt][rh * 2 + 1] + bb.y, 0.0f);
                *(float2*)(out + (size_t)m * DDIM + n) = make_float2(v0, v1);
            }
}

// ---------------------------------------------------------------------------
extern "C" void kernel_launch(void* const* d_in, const int* in_sizes, int n_in,
                              void* d_out, int out_size)
{
    const float* queries = (const float*)d_in[0];  // [32,20,64,512]
    const float* keys    = (const float*)d_in[1];  // [32,256,512]
    const float* qmask   = (const float*)d_in[2];  // [32,20,64]
    const float* kmask   = (const float*)d_in[3];  // [32,256]
    const float* Wm      = (const float*)d_in[4];  // [512,1024]
    const float* bias    = (const float*)d_in[5];  // [512]
    float* out = (float*)d_out;                    // [32,256,512]

    cudaFuncSetAttribute(k_hm1, cudaFuncAttributeMaxDynamicSharedMemorySize, SMEM_BYTES);
    cudaFuncSetAttribute(k_hm2, cudaFuncAttributeMaxDynamicSharedMemorySize, SMEM_BYTES);
    cudaFuncSetAttribute(k_hm3, cudaFuncAttributeMaxDynamicSharedMemorySize, SMEM_BYTES);

    conv_keys<<<4096, 256>>>(keys);
    conv_q   <<<20480, 256>>>(queries);
    conv_qt  <<<dim3(NJ / 64, DDIM / 32, BATCH), 256>>>(queries);
    conv_w   <<<512, 256>>>(Wm);

    k_hm1<<<dim3(NJ / 128, LSEQ / 128, BATCH), 256, SMEM_BYTES>>>();
    k_softmax<<<MROWS, 256>>>(qmask, kmask);
    k_hm2<<<dim3(DDIM / 128, LSEQ / 128, BATCH), 256, SMEM_BYTES>>>(keys);
    k_hm3<<<dim3(DDIM / 128, MROWS / 128, 1), 256, SMEM_BYTES>>>(bias, out);
}

// round 9
// speedup vs baseline: 1.7651x; 1.0256x over previous
#include <cuda_runtime.h>
#include <cuda_bf16.h>
#include <stdint.h>
#include <math.h>

// Shapes
#define BATCH 32
#define NTURN 20
#define JTOK  64
#define LSEQ  256
#define DDIM  512
#define NJ    1280
#define MROWS 8192
#define NEGV  (-4294967295.0f)

// Compact split scratch (hi/lo; pattern A=[hi,hi,lo], B=[hi,lo,hi] applied per chunk)
__device__ __align__(16) __nv_bfloat16 g_Khi [(size_t)BATCH*LSEQ*DDIM];
__device__ __align__(16) __nv_bfloat16 g_Klo [(size_t)BATCH*LSEQ*DDIM];
__device__ __align__(16) __nv_bfloat16 g_Qhi [(size_t)BATCH*NJ*DDIM];
__device__ __align__(16) __nv_bfloat16 g_Qlo [(size_t)BATCH*NJ*DDIM];
__device__ __align__(16) __nv_bfloat16 g_Qthi[(size_t)BATCH*DDIM*NJ];   // transposed [b][d][j]
__device__ __align__(16) __nv_bfloat16 g_Qtlo[(size_t)BATCH*DDIM*NJ];
__device__ __align__(16) float         g_S   [(size_t)BATCH*LSEQ*NJ];
__device__ __align__(16) __nv_bfloat16 g_Chi [(size_t)BATCH*LSEQ*NJ];
__device__ __align__(16) __nv_bfloat16 g_Clo [(size_t)BATCH*LSEQ*NJ];
__device__ __align__(16) __nv_bfloat16 g_Fhi [(size_t)MROWS*1024];
__device__ __align__(16) __nv_bfloat16 g_Flo [(size_t)MROWS*1024];
__device__ __align__(16) __nv_bfloat16 g_Whi [(size_t)DDIM*1024];
__device__ __align__(16) __nv_bfloat16 g_Wlo [(size_t)DDIM*1024];

// ---------------------------------------------------------------------------
// helpers
// ---------------------------------------------------------------------------
__device__ __forceinline__ uint32_t smem_u32(const void* p) {
    uint32_t a;
    asm("{ .reg .u64 t; cvta.to.shared.u64 t, %1; cvt.u32.u64 %0, t; }" : "=r"(a) : "l"(p));
    return a;
}
__device__ __forceinline__ void split_bf(float x, __nv_bfloat16& h, __nv_bfloat16& l) {
    h = __float2bfloat16(x);
    l = __float2bfloat16(x - __bfloat162float(h));
}
__device__ __forceinline__ void cpa16(uint32_t saddr, const void* g) {
    asm volatile("cp.async.cg.shared.global [%0], [%1], 16;" :: "r"(saddr), "l"(g));
}
#define CP_COMMIT() asm volatile("cp.async.commit_group;")
#define CP_WAIT0()  asm volatile("cp.async.wait_group 0;")
#define CP_WAIT1()  asm volatile("cp.async.wait_group 1;")

#define LDSM4(R, ADDR) \
    asm volatile("ldmatrix.sync.aligned.m8n8.x4.shared.b16 {%0,%1,%2,%3}, [%4];" \
        : "=r"((R)[0]), "=r"((R)[1]), "=r"((R)[2]), "=r"((R)[3]) : "r"(ADDR))

#define MMA16816(C, A, B0, B1) \
    asm volatile("mma.sync.aligned.m16n8k16.row.col.f32.bf16.bf16.f32 " \
        "{%0,%1,%2,%3},{%4,%5,%6,%7},{%8,%9},{%0,%1,%2,%3};" \
        : "+f"((C)[0]), "+f"((C)[1]), "+f"((C)[2]), "+f"((C)[3]) \
        : "r"((A)[0]), "r"((A)[1]), "r"((A)[2]), "r"((A)[3]), "r"(B0), "r"(B1))

// smem: 3 stages x (A tile + B tile); tile = 128 rows x 64 K-cols, PITCH 72 bf16
#define PITCH 72
#define ATILE (128 * PITCH * 2)           // 18432 B
#define STAGES 3
#define SMEM_BYTES (2 * STAGES * ATILE)   // 110592 B (2 CTAs/SM = 221KB)

// pattern selectors
__device__ __forceinline__ const __nv_bfloat16* selA(const __nv_bfloat16* hi, const __nv_bfloat16* lo, int c, int bl) {
    return (c / bl) < 2 ? hi : lo;        // [hi|hi|lo]
}
__device__ __forceinline__ const __nv_bfloat16* selB(const __nv_bfloat16* hi, const __nv_bfloat16* lo, int c, int bl) {
    return (c / bl) == 1 ? lo : hi;       // [hi|lo|hi]
}

// ---------------------------------------------------------------------------
// load one K=64 chunk of A and B tiles into stage
// ---------------------------------------------------------------------------
__device__ __forceinline__ void load_tiles(uint32_t sb, int stage,
                                           const __nv_bfloat16* A, int lda,
                                           const __nv_bfloat16* B, int ldb, int koff)
{
    const int tid = threadIdx.x;
    const uint32_t sA = sb + stage * ATILE;
    const uint32_t sB = sb + STAGES * ATILE + stage * ATILE;
    #pragma unroll
    for (int i = 0; i < 4; ++i) {
        int id = tid + i * 256;           // 1024 x 16B = 128 rows x 64 cols x 2B
        int r = id >> 3, cc = id & 7;
        cpa16(sA + (uint32_t)(r * PITCH + cc * 8) * 2, A + (size_t)r * lda + koff + cc * 8);
    }
    #pragma unroll
    for (int i = 0; i < 4; ++i) {
        int id = tid + i * 256;
        int r = id >> 3, cc = id & 7;
        cpa16(sB + (uint32_t)(r * PITCH + cc * 8) * 2, B + (size_t)r * ldb + koff + cc * 8);
    }
}

__device__ __forceinline__ void hmma_compute(uint32_t sb, int stage,
                                             int lane, int wm0, int wn0,
                                             float acc[4][4][4])
{
    const uint32_t sA = sb + stage * ATILE;
    const uint32_t sB = sb + STAGES * ATILE + stage * ATILE;
    const int rowoff = lane & 15;
    #pragma unroll
    for (int ks = 0; ks < 4; ++ks) {
        const int coloff = ks * 16 + (lane >> 4) * 8;
        uint32_t a[4][4], b[2][4];
        #pragma unroll
        for (int mt = 0; mt < 4; ++mt)
            LDSM4(a[mt], sA + (uint32_t)((wm0 + mt * 16 + rowoff) * PITCH + coloff) * 2);
        #pragma unroll
        for (int np = 0; np < 2; ++np)
            LDSM4(b[np], sB + (uint32_t)((wn0 + np * 16 + rowoff) * PITCH + coloff) * 2);
        #pragma unroll
        for (int mt = 0; mt < 4; ++mt)
            #pragma unroll
            for (int nt = 0; nt < 4; ++nt)
                MMA16816(acc[mt][nt], a[mt], b[nt >> 1][nt & 1], b[nt >> 1][2 + (nt & 1)]);
    }
}

// 3-stage pipelined mainloop, one __syncthreads per K=64 chunk.
// bl = Kreal/64; total chunks = 3*bl (split pattern across blocks).
__device__ __forceinline__ void hmma_loop(char* smem,
                                          const __nv_bfloat16* Ahi, const __nv_bfloat16* Alo, int lda,
                                          const __nv_bfloat16* Bhi, const __nv_bfloat16* Blo, int ldb,
                                          int bl, float acc[4][4][4])
{
    const int tid = threadIdx.x;
    const int lane = tid & 31, wid = tid >> 5;
    const int wm0 = (wid >> 2) * 64, wn0 = (wid & 3) * 32;
    const uint32_t sb = smem_u32(smem);
    const int nch = 3 * bl;

    load_tiles(sb, 0, selA(Ahi, Alo, 0, bl), lda, selB(Bhi, Blo, 0, bl), ldb, 0);
    CP_COMMIT();
    load_tiles(sb, 1, selA(Ahi, Alo, 1, bl), lda, selB(Bhi, Blo, 1, bl), ldb, (1 % bl) * 64);
    CP_COMMIT();

    for (int c = 0; c < nch; ++c) {
        if (c + 1 < nch) { CP_WAIT1(); } else { CP_WAIT0(); }
        __syncthreads();          // stage c ready everywhere; compute(c-1) done everywhere
        if (c + 2 < nch) {
            int cn = c + 2;
            load_tiles(sb, cn % STAGES, selA(Ahi, Alo, cn, bl), lda,
                       selB(Bhi, Blo, cn, bl), ldb, (cn % bl) * 64);
            CP_COMMIT();
        }
        hmma_compute(sb, c % STAGES, lane, wm0, wn0, acc);
    }
}

// ---------------------------------------------------------------------------
// Conversion kernels (fp32 -> compact hi/lo bf16)
// ---------------------------------------------------------------------------
__device__ __forceinline__ void split4_store(const float4 v, __nv_bfloat16* hi, __nv_bfloat16* lo, size_t o)
{
    __nv_bfloat16 h[4], l[4];
    split_bf(v.x, h[0], l[0]); split_bf(v.y, h[1], l[1]);
    split_bf(v.z, h[2], l[2]); split_bf(v.w, h[3], l[3]);
    __nv_bfloat162 hh0, hh1, ll0, ll1;
    hh0.x = h[0]; hh0.y = h[1]; hh1.x = h[2]; hh1.y = h[3];
    ll0.x = l[0]; ll0.y = l[1]; ll1.x = l[2]; ll1.y = l[3];
    *(__nv_bfloat162*)(hi + o) = hh0; *(__nv_bfloat162*)(hi + o + 2) = hh1;
    *(__nv_bfloat162*)(lo + o) = ll0; *(__nv_bfloat162*)(lo + o + 2) = ll1;
}

__global__ __launch_bounds__(256) void conv_keys(const float* __restrict__ keys)
{
    size_t t = (size_t)blockIdx.x * 256 + threadIdx.x;
    size_t o = t * 4;
    split4_store(*(const float4*)(keys + o), g_Khi, g_Klo, o);
}
__global__ __launch_bounds__(256) void conv_w(const float* __restrict__ Wm)
{
    size_t t = (size_t)blockIdx.x * 256 + threadIdx.x;
    size_t o = t * 4;
    split4_store(*(const float4*)(Wm + o), g_Whi, g_Wlo, o);
}

// Merged split + transpose: q[b][j][d] -> Q{hi,lo}[b][j][d] AND Qt{hi,lo}[b][d][j].
// Tile: 64 j x 32 d.
__global__ __launch_bounds__(256) void conv_qt(const float* __restrict__ q)
{
    __shared__ __nv_bfloat16 shh[32][72];
    __shared__ __nv_bfloat16 shl[32][72];
    const int b  = blockIdx.z;
    const int d0 = blockIdx.y * 32;
    const int j0 = blockIdx.x * 64;
    const int t  = threadIdx.x;

    #pragma unroll
    for (int i = 0; i < 2; ++i) {
        int jj = (t >> 3) + i * 32;               // 0..63
        int dd = (t & 7) * 4;                     // 0..28
        size_t qo = ((size_t)b * NJ + j0 + jj) * DDIM + d0 + dd;
        float4 v = *(const float4*)(q + qo);
        __nv_bfloat16 h0, l0, h1, l1, h2, l2, h3, l3;
        split_bf(v.x, h0, l0); split_bf(v.y, h1, l1);
        split_bf(v.z, h2, l2); split_bf(v.w, h3, l3);
        // straight layout (8B per thread, 64B contiguous per 8 threads)
        __nv_bfloat162 hp0, hp1, lp0, lp1;
        hp0.x = h0; hp0.y = h1; hp1.x = h2; hp1.y = h3;
        lp0.x = l0; lp0.y = l1; lp1.x = l2; lp1.y = l3;
        *(__nv_bfloat162*)(g_Qhi + qo)     = hp0; *(__nv_bfloat162*)(g_Qhi + qo + 2) = hp1;
        *(__nv_bfloat162*)(g_Qlo + qo)     = lp0; *(__nv_bfloat162*)(g_Qlo + qo + 2) = lp1;
        // transpose staging
        shh[dd+0][jj] = h0; shl[dd+0][jj] = l0;
        shh[dd+1][jj] = h1; shl[dd+1][jj] = l1;
        shh[dd+2][jj] = h2; shl[dd+2][jj] = l2;
        shh[dd+3][jj] = h3; shl[dd+3][jj] = l3;
    }
    __syncthreads();

    const int r  = t >> 3;                        // 0..31 (d row)
    const int pc = t & 7;                         // 8 bf16 = 16B chunk
    size_t o = ((size_t)b * DDIM + d0 + r) * NJ + j0 + pc * 8;
    *(uint4*)(g_Qthi + o) = *(const uint4*)&shh[r][pc * 8];
    *(uint4*)(g_Qtlo + o) = *(const uint4*)&shl[r][pc * 8];
}

// ---------------------------------------------------------------------------
// GEMM1: scores[b] = keys x queries^T  (M=256, N=1280, Kreal=512) -> g_S
// ---------------------------------------------------------------------------
__global__ __launch_bounds__(256, 2) void k_hm1()
{
    extern __shared__ char smem[];
    const int b = blockIdx.z, m0 = blockIdx.y * 128, n0 = blockIdx.x * 128;
    const __nv_bfloat16* Ah = g_Khi + ((size_t)b * LSEQ + m0) * DDIM;
    const __nv_bfloat16* Al = g_Klo + ((size_t)b * LSEQ + m0) * DDIM;
    const __nv_bfloat16* Bh = g_Qhi + ((size_t)b * NJ + n0) * DDIM;
    const __nv_bfloat16* Bl = g_Qlo + ((size_t)b * NJ + n0) * DDIM;
    float acc[4][4][4] = {};
    hmma_loop(smem, Ah, Al, DDIM, Bh, Bl, DDIM, DDIM / 64, acc);

    const int lane = threadIdx.x & 31, wid = threadIdx.x >> 5;
    const int wm0 = (wid >> 2) * 64, wn0 = (wid & 3) * 32;
    float* C = g_S + (size_t)b * LSEQ * NJ;
    #pragma unroll
    for (int mt = 0; mt < 4; ++mt)
        #pragma unroll
        for (int nt = 0; nt < 4; ++nt)
            #pragma unroll
            for (int rh = 0; rh < 2; ++rh) {
                int m = m0 + wm0 + mt * 16 + (lane >> 2) + rh * 8;
                int n = n0 + wn0 + nt * 8 + (lane & 3) * 2;
                *(float2*)(C + (size_t)m * NJ + n) =
                    make_float2(acc[mt][nt][rh * 2], acc[mt][nt][rh * 2 + 1]);
            }
}

// ---------------------------------------------------------------------------
// Softmax + combined weights -> g_Chi / g_Clo
// ---------------------------------------------------------------------------
__global__ __launch_bounds__(256) void k_softmax(const float* __restrict__ qmask,
                                                 const float* __restrict__ kmask)
{
    const int row = blockIdx.x;
    const int b   = row >> 8;

    __shared__ float buf[NJ];
    __shared__ float qm[NJ];
    __shared__ float sim2[32];
    __shared__ float tvalid[32];
    __shared__ float wn[NTURN];

    const int tid = threadIdx.x;
    const float* srow = g_S + (size_t)row * NJ;
    const float* qmrow = qmask + b * NJ;

    for (int j = tid; j < NJ; j += 256) { buf[j] = srow[j]; qm[j] = qmrow[j]; }
    __syncthreads();

    const int wid = tid >> 5, lane = tid & 31;
    for (int n = wid; n < NTURN; n += 8) {
        const int base = n * JTOK;
        float q1 = qm[base + lane],  q2 = qm[base + 32 + lane];
        float s1 = buf[base + lane], s2 = buf[base + 32 + lane];
        float x1 = (q1 == 0.0f) ? NEGV : s1;
        float x2 = (q2 == 0.0f) ? NEGV : s2;
        float mx = fmaxf(x1, x2);
        #pragma unroll
        for (int o = 16; o; o >>= 1) mx = fmaxf(mx, __shfl_xor_sync(0xFFFFFFFFu, mx, o));
        float e1 = __expf(x1 - mx), e2 = __expf(x2 - mx);
        float es = e1 + e2, qs = q1 + q2, sp = e1 * s1 + e2 * s2;
        #pragma unroll
        for (int o = 16; o; o >>= 1) {
            es += __shfl_xor_sync(0xFFFFFFFFu, es, o);
            qs += __shfl_xor_sync(0xFFFFFFFFu, qs, o);
            sp += __shfl_xor_sync(0xFFFFFFFFu, sp, o);
        }
        float inv = 1.0f / es;
        buf[base + lane]      = e1 * inv;
        buf[base + 32 + lane] = e2 * inv;
        if (lane == 0) { sim2[n] = sp * inv; tvalid[n] = qs; }
    }
    __syncthreads();

    if (wid == 0) {
        float v = (lane < NTURN && tvalid[lane] != 0.0f) ? sim2[lane] : NEGV;
        float mx = v;
        #pragma unroll
        for (int o = 16; o; o >>= 1) mx = fmaxf(mx, __shfl_xor_sync(0xFFFFFFFFu, mx, o));
        float e = (lane < NTURN) ? __expf(v - mx) : 0.0f;
        float es = e;
        #pragma unroll
        for (int o = 16; o; o >>= 1) es += __shfl_xor_sync(0xFFFFFFFFu, es, o);
        if (lane < NTURN) wn[lane] = e / es;
    }
    __syncthreads();

    const float m = kmask[row];
    for (int idx = tid; idx < NJ; idx += 256) {
        const int n = idx >> 6;
        float c = m * wn[n] * buf[idx];
        __nv_bfloat16 h, l; split_bf(c, h, l);
        g_Chi[(size_t)row * NJ + idx] = h;
        g_Clo[(size_t)row * NJ + idx] = l;
    }
}

// ---------------------------------------------------------------------------
// GEMM2: attn[b] = C x queries (M=256, N=512, Kreal=1280) -> g_Fhi/g_Flo
// B side uses pre-transposed Qt[d][j] (K-major) -> plain cp.async loads.
// ---------------------------------------------------------------------------
__global__ __launch_bounds__(256, 2) void k_hm2(const float* __restrict__ keys)
{
    extern __shared__ char smem[];
    const int b = blockIdx.z, m0 = blockIdx.y * 128, n0 = blockIdx.x * 128;
    const __nv_bfloat16* Ah = g_Chi  + ((size_t)b * LSEQ + m0) * NJ;
    const __nv_bfloat16* Al = g_Clo  + ((size_t)b * LSEQ + m0) * NJ;
    const __nv_bfloat16* Bh = g_Qthi + ((size_t)b * DDIM + n0) * NJ;
    const __nv_bfloat16* Bl = g_Qtlo + ((size_t)b * DDIM + n0) * NJ;
    float acc[4][4][4] = {};
    hmma_loop(smem, Ah, Al, NJ, Bh, Bl, NJ, NJ / 64, acc);

    const int lane = threadIdx.x & 31, wid = threadIdx.x >> 5;
    const int wm0 = (wid >> 2) * 64, wn0 = (wid & 3) * 32;
    const float* keyb = keys + (size_t)b * LSEQ * DDIM;
    #pragma unroll
    for (int mt = 0; mt < 4; ++mt)
        #pragma unroll
        for (int nt = 0; nt < 4; ++nt)
            #pragma unroll
            for (int rh = 0; rh < 2; ++rh) {
                int m = m0 + wm0 + mt * 16 + (lane >> 2) + rh * 8;
                int n = n0 + wn0 + nt * 8 + (lane & 3) * 2;
                float a0 = acc[mt][nt][rh * 2], a1 = acc[mt][nt][rh * 2 + 1];
                float2 kv = *(const float2*)(keyb + (size_t)m * DDIM + n);
                float mu0 = a0 * kv.x, mu1 = a1 * kv.y;
                float df0 = a0 - kv.x, df1 = a1 - kv.y;
                float sq0 = df0 * df0, sq1 = df1 * df1;
                size_t rowo = ((size_t)b * LSEQ + m) * 1024;
                __nv_bfloat16 h0, l0, h1, l1;
                __nv_bfloat162 hp, lp;
                split_bf(mu0, h0, l0); split_bf(mu1, h1, l1);
                hp.x = h0; hp.y = h1; lp.x = l0; lp.y = l1;
                *(__nv_bfloat162*)(g_Fhi + rowo + n) = hp;
                *(__nv_bfloat162*)(g_Flo + rowo + n) = lp;
                split_bf(sq0, h0, l0); split_bf(sq1, h1, l1);
                hp.x = h0; hp.y = h1; lp.x = l0; lp.y = l1;
                *(__nv_bfloat162*)(g_Fhi + rowo + 512 + n) = hp;
                *(__nv_bfloat162*)(g_Flo + rowo + 512 + n) = lp;
            }
}

// ---------------------------------------------------------------------------
// GEMM3: out = relu(F x W^T + b)  (M=8192, N=512, Kreal=1024)
// ---------------------------------------------------------------------------
__global__ __launch_bounds__(256, 2) void k_hm3(const float* __restrict__ bias,
                                                float* __restrict__ out)
{
    extern __shared__ char smem[];
    const int m0 = blockIdx.y * 128, n0 = blockIdx.x * 128;
    const __nv_bfloat16* Ah = g_Fhi + (size_t)m0 * 1024;
    const __nv_bfloat16* Al = g_Flo + (size_t)m0 * 1024;
    const __nv_bfloat16* Bh = g_Whi + (size_t)n0 * 1024;
    const __nv_bfloat16* Bl = g_Wlo + (size_t)n0 * 1024;
    float acc[4][4][4] = {};
    hmma_loop(smem, Ah, Al, 1024, Bh, Bl, 1024, 1024 / 64, acc);

    const int lane = threadIdx.x & 31, wid = threadIdx.x >> 5;
    const int wm0 = (wid >> 2) * 64, wn0 = (wid & 3) * 32;
    #pragma unroll
    for (int mt = 0; mt < 4; ++mt)
        #pragma unroll
        for (int nt = 0; nt < 4; ++nt)
            #pragma unroll
            for (int rh = 0; rh < 2; ++rh) {
                int m = m0 + wm0 + mt * 16 + (lane >> 2) + rh * 8;
                int n = n0 + wn0 + nt * 8 + (lane & 3) * 2;
                float2 bb = *(const float2*)(bias + n);
                float v0 = fmaxf(acc[mt][nt][rh * 2]     + bb.x, 0.0f);
                float v1 = fmaxf(acc[mt][nt][rh * 2 + 1] + bb.y, 0.0f);
                *(float2*)(out + (size_t)m * DDIM + n) = make_float2(v0, v1);
            }
}

// ---------------------------------------------------------------------------
extern "C" void kernel_launch(void* const* d_in, const int* in_sizes, int n_in,
                              void* d_out, int out_size)
{
    const float* queries = (const float*)d_in[0];  // [32,20,64,512]
    const float* keys    = (const float*)d_in[1];  // [32,256,512]
    const float* qmask   = (const float*)d_in[2];  // [32,20,64]
    const float* kmask   = (const float*)d_in[3];  // [32,256]
    const float* Wm      = (const float*)d_in[4];  // [512,1024]
    const float* bias    = (const float*)d_in[5];  // [512]
    float* out = (float*)d_out;                    // [32,256,512]

    cudaFuncSetAttribute(k_hm1, cudaFuncAttributeMaxDynamicSharedMemorySize, SMEM_BYTES);
    cudaFuncSetAttribute(k_hm2, cudaFuncAttributeMaxDynamicSharedMemorySize, SMEM_BYTES);
    cudaFuncSetAttribute(k_hm3, cudaFuncAttributeMaxDynamicSharedMemorySize, SMEM_BYTES);

    conv_keys<<<4096, 256>>>(keys);
    conv_qt  <<<dim3(NJ / 64, DDIM / 32, BATCH), 256>>>(queries);
    conv_w   <<<512, 256>>>(Wm);

    k_hm1<<<dim3(NJ / 128, LSEQ / 128, BATCH), 256, SMEM_BYTES>>>();
    k_softmax<<<MROWS, 256>>>(qmask, kmask);
    k_hm2<<<dim3(DDIM / 128, LSEQ / 128, BATCH), 256, SMEM_BYTES>>>(keys);
    k_hm3<<<dim3(DDIM / 128, MROWS / 128, 1), 256, SMEM_BYTES>>>(bias, out);
}

// round 10
// speedup vs baseline: 1.8286x; 1.0360x over previous
#include <cuda_runtime.h>
#include <cuda_bf16.h>
#include <stdint.h>
#include <math.h>

// Shapes
#define BATCH 32
#define NTURN 20
#define JTOK  64
#define LSEQ  256
#define DDIM  512
#define NJ    1280
#define MROWS 8192
#define NEGV  (-4294967295.0f)

// Compact split scratch (hi/lo)
__device__ __align__(16) __nv_bfloat16 g_Khi [(size_t)BATCH*LSEQ*DDIM];
__device__ __align__(16) __nv_bfloat16 g_Klo [(size_t)BATCH*LSEQ*DDIM];
__device__ __align__(16) __nv_bfloat16 g_Qhi [(size_t)BATCH*NJ*DDIM];
__device__ __align__(16) __nv_bfloat16 g_Qlo [(size_t)BATCH*NJ*DDIM];
__device__ __align__(16) __nv_bfloat16 g_Qthi[(size_t)BATCH*DDIM*NJ];   // transposed [b][d][j]
__device__ __align__(16) __nv_bfloat16 g_Qtlo[(size_t)BATCH*DDIM*NJ];
__device__ __align__(16) float         g_S   [(size_t)BATCH*LSEQ*NJ];
__device__ __align__(16) __nv_bfloat16 g_Chi [(size_t)BATCH*LSEQ*NJ];
__device__ __align__(16) __nv_bfloat16 g_Clo [(size_t)BATCH*LSEQ*NJ];
__device__ __align__(16) __nv_bfloat16 g_Fhi [(size_t)MROWS*1024];
__device__ __align__(16) __nv_bfloat16 g_Flo [(size_t)MROWS*1024];
__device__ __align__(16) __nv_bfloat16 g_Whi [(size_t)DDIM*1024];
__device__ __align__(16) __nv_bfloat16 g_Wlo [(size_t)DDIM*1024];

// ---------------------------------------------------------------------------
// helpers
// ---------------------------------------------------------------------------
__device__ __forceinline__ uint32_t smem_u32(const void* p) {
    uint32_t a;
    asm("{ .reg .u64 t; cvta.to.shared.u64 t, %1; cvt.u32.u64 %0, t; }" : "=r"(a) : "l"(p));
    return a;
}
__device__ __forceinline__ void split_bf(float x, __nv_bfloat16& h, __nv_bfloat16& l) {
    h = __float2bfloat16(x);
    l = __float2bfloat16(x - __bfloat162float(h));
}
__device__ __forceinline__ void cpa16(uint32_t saddr, const void* g) {
    asm volatile("cp.async.cg.shared.global [%0], [%1], 16;" :: "r"(saddr), "l"(g));
}
#define CP_COMMIT() asm volatile("cp.async.commit_group;")
#define CP_WAIT0()  asm volatile("cp.async.wait_group 0;")

#define LDSM4(R, ADDR) \
    asm volatile("ldmatrix.sync.aligned.m8n8.x4.shared.b16 {%0,%1,%2,%3}, [%4];" \
        : "=r"((R)[0]), "=r"((R)[1]), "=r"((R)[2]), "=r"((R)[3]) : "r"(ADDR))

#define MMA16816(C, A, B0, B1) \
    asm volatile("mma.sync.aligned.m16n8k16.row.col.f32.bf16.bf16.f32 " \
        "{%0,%1,%2,%3},{%4,%5,%6,%7},{%8,%9},{%0,%1,%2,%3};" \
        : "+f"((C)[0]), "+f"((C)[1]), "+f"((C)[2]), "+f"((C)[3]) \
        : "r"((A)[0]), "r"((A)[1]), "r"((A)[2]), "r"((A)[3]), "r"(B0), "r"(B1))

// smem: 2 stages x 4 tiles (A_hi, A_lo, B_hi, B_lo); tile = 128 rows x 32 K-cols
#define PITCH 40
#define TILE  (128 * PITCH * 2)           // 10240 B
#define STG   (4 * TILE)                  // 40960 B per stage
#define SMEM_BYTES (2 * STG)              // 81920 B (2 CTAs/SM = 160KB)

// ---------------------------------------------------------------------------
// load one K=32 chunk: 4 tiles (A_hi, A_lo, B_hi, B_lo)
// ---------------------------------------------------------------------------
__device__ __forceinline__ void load_tiles4(uint32_t sb, int stage,
                                            const __nv_bfloat16* Ah, const __nv_bfloat16* Al, int lda,
                                            const __nv_bfloat16* Bh, const __nv_bfloat16* Bl, int ldb,
                                            int koff)
{
    const int tid = threadIdx.x;
    const uint32_t s0 = sb + stage * STG;
    // each tile: 128 rows x 32 cols x 2B = 8192B = 512 x 16B; 2 iters of 256 thr
    #pragma unroll
    for (int i = 0; i < 2; ++i) {
        int id = tid + i * 256;
        int r = id >> 2, cc = id & 3;
        uint32_t so = (uint32_t)(r * PITCH + cc * 8) * 2;
        size_t goA = (size_t)r * lda + koff + cc * 8;
        size_t goB = (size_t)r * ldb + koff + cc * 8;
        cpa16(s0 + so,            Ah + goA);
        cpa16(s0 + TILE + so,     Al + goA);
        cpa16(s0 + 2 * TILE + so, Bh + goB);
        cpa16(s0 + 3 * TILE + so, Bl + goB);
    }
}

// per K=32 chunk: 2 k16 steps; per step load b_hi/b_lo frags, then per mt row:
// a_hi, a_lo frags + 3 MMA combos (hi*hi, hi*lo, lo*hi) into same acc.
__device__ __forceinline__ void hmma_compute4(uint32_t sb, int stage,
                                              int lane, int wm0, int wn0,
                                              float acc[4][4][4])
{
    const uint32_t sAh = sb + stage * STG;
    const uint32_t sAl = sAh + TILE;
    const uint32_t sBh = sAh + 2 * TILE;
    const uint32_t sBl = sAh + 3 * TILE;
    const int rowoff = lane & 15;
    #pragma unroll
    for (int ks = 0; ks < 2; ++ks) {
        const int coloff = ks * 16 + (lane >> 4) * 8;
        uint32_t bh[2][4], blo[2][4];
        #pragma unroll
        for (int np = 0; np < 2; ++np) {
            uint32_t bo = (uint32_t)((wn0 + np * 16 + rowoff) * PITCH + coloff) * 2;
            LDSM4(bh[np],  sBh + bo);
            LDSM4(blo[np], sBl + bo);
        }
        #pragma unroll
        for (int mt = 0; mt < 4; ++mt) {
            uint32_t ah[4], al[4];
            uint32_t ao = (uint32_t)((wm0 + mt * 16 + rowoff) * PITCH + coloff) * 2;
            LDSM4(ah, sAh + ao);
            LDSM4(al, sAl + ao);
            #pragma unroll
            for (int nt = 0; nt < 4; ++nt) {
                MMA16816(acc[mt][nt], ah, bh[nt >> 1][nt & 1],  bh[nt >> 1][2 + (nt & 1)]);
                MMA16816(acc[mt][nt], ah, blo[nt >> 1][nt & 1], blo[nt >> 1][2 + (nt & 1)]);
                MMA16816(acc[mt][nt], al, bh[nt >> 1][nt & 1],  bh[nt >> 1][2 + (nt & 1)]);
            }
        }
    }
}

// 2-stage pipelined mainloop over bl K=32 chunks; one __syncthreads per chunk.
__device__ __forceinline__ void hmma_loop4(char* smem,
                                           const __nv_bfloat16* Ahi, const __nv_bfloat16* Alo, int lda,
                                           const __nv_bfloat16* Bhi, const __nv_bfloat16* Blo, int ldb,
                                           int bl, float acc[4][4][4])
{
    const int tid = threadIdx.x;
    const int lane = tid & 31, wid = tid >> 5;
    const int wm0 = (wid >> 2) * 64, wn0 = (wid & 3) * 32;
    const uint32_t sb = smem_u32(smem);

    load_tiles4(sb, 0, Ahi, Alo, lda, Bhi, Blo, ldb, 0);
    CP_COMMIT();

    for (int c = 0; c < bl; ++c) {
        CP_WAIT0();
        __syncthreads();          // stage c ready everywhere; compute(c-1) done everywhere
        if (c + 1 < bl) {
            load_tiles4(sb, (c + 1) & 1, Ahi, Alo, lda, Bhi, Blo, ldb, (c + 1) * 32);
            CP_COMMIT();
        }
        hmma_compute4(sb, c & 1, lane, wm0, wn0, acc);
    }
}

// ---------------------------------------------------------------------------
// Conversion kernels (fp32 -> compact hi/lo bf16)
// ---------------------------------------------------------------------------
__device__ __forceinline__ void split4_store(const float4 v, __nv_bfloat16* hi, __nv_bfloat16* lo, size_t o)
{
    __nv_bfloat16 h[4], l[4];
    split_bf(v.x, h[0], l[0]); split_bf(v.y, h[1], l[1]);
    split_bf(v.z, h[2], l[2]); split_bf(v.w, h[3], l[3]);
    __nv_bfloat162 hh0, hh1, ll0, ll1;
    hh0.x = h[0]; hh0.y = h[1]; hh1.x = h[2]; hh1.y = h[3];
    ll0.x = l[0]; ll0.y = l[1]; ll1.x = l[2]; ll1.y = l[3];
    *(__nv_bfloat162*)(hi + o) = hh0; *(__nv_bfloat162*)(hi + o + 2) = hh1;
    *(__nv_bfloat162*)(lo + o) = ll0; *(__nv_bfloat162*)(lo + o + 2) = ll1;
}

__global__ __launch_bounds__(256) void conv_keys(const float* __restrict__ keys)
{
    size_t t = (size_t)blockIdx.x * 256 + threadIdx.x;
    size_t o = t * 4;
    split4_store(*(const float4*)(keys + o), g_Khi, g_Klo, o);
}
__global__ __launch_bounds__(256) void conv_w(const float* __restrict__ Wm)
{
    size_t t = (size_t)blockIdx.x * 256 + threadIdx.x;
    size_t o = t * 4;
    split4_store(*(const float4*)(Wm + o), g_Whi, g_Wlo, o);
}

// Merged split + transpose: q[b][j][d] -> Q{hi,lo}[b][j][d] AND Qt{hi,lo}[b][d][j].
__global__ __launch_bounds__(256) void conv_qt(const float* __restrict__ q)
{
    __shared__ __nv_bfloat16 shh[32][72];
    __shared__ __nv_bfloat16 shl[32][72];
    const int b  = blockIdx.z;
    const int d0 = blockIdx.y * 32;
    const int j0 = blockIdx.x * 64;
    const int t  = threadIdx.x;

    #pragma unroll
    for (int i = 0; i < 2; ++i) {
        int jj = (t >> 3) + i * 32;               // 0..63
        int dd = (t & 7) * 4;                     // 0..28
        size_t qo = ((size_t)b * NJ + j0 + jj) * DDIM + d0 + dd;
        float4 v = *(const float4*)(q + qo);
        __nv_bfloat16 h0, l0, h1, l1, h2, l2, h3, l3;
        split_bf(v.x, h0, l0); split_bf(v.y, h1, l1);
        split_bf(v.z, h2, l2); split_bf(v.w, h3, l3);
        __nv_bfloat162 hp0, hp1, lp0, lp1;
        hp0.x = h0; hp0.y = h1; hp1.x = h2; hp1.y = h3;
        lp0.x = l0; lp0.y = l1; lp1.x = l2; lp1.y = l3;
        *(__nv_bfloat162*)(g_Qhi + qo)     = hp0; *(__nv_bfloat162*)(g_Qhi + qo + 2) = hp1;
        *(__nv_bfloat162*)(g_Qlo + qo)     = lp0; *(__nv_bfloat162*)(g_Qlo + qo + 2) = lp1;
        shh[dd+0][jj] = h0; shl[dd+0][jj] = l0;
        shh[dd+1][jj] = h1; shl[dd+1][jj] = l1;
        shh[dd+2][jj] = h2; shl[dd+2][jj] = l2;
        shh[dd+3][jj] = h3; shl[dd+3][jj] = l3;
    }
    __syncthreads();

    const int r  = t >> 3;                        // 0..31 (d row)
    const int pc = t & 7;                         // 8 bf16 = 16B chunk
    size_t o = ((size_t)b * DDIM + d0 + r) * NJ + j0 + pc * 8;
    *(uint4*)(g_Qthi + o) = *(const uint4*)&shh[r][pc * 8];
    *(uint4*)(g_Qtlo + o) = *(const uint4*)&shl[r][pc * 8];
}

// ---------------------------------------------------------------------------
// GEMM1: scores[b] = keys x queries^T  (M=256, N=1280, K=512) -> g_S
// ---------------------------------------------------------------------------
__global__ __launch_bounds__(256, 2) void k_hm1()
{
    extern __shared__ char smem[];
    const int b = blockIdx.z, m0 = blockIdx.y * 128, n0 = blockIdx.x * 128;
    const __nv_bfloat16* Ah = g_Khi + ((size_t)b * LSEQ + m0) * DDIM;
    const __nv_bfloat16* Al = g_Klo + ((size_t)b * LSEQ + m0) * DDIM;
    const __nv_bfloat16* Bh = g_Qhi + ((size_t)b * NJ + n0) * DDIM;
    const __nv_bfloat16* Bl = g_Qlo + ((size_t)b * NJ + n0) * DDIM;
    float acc[4][4][4] = {};
    hmma_loop4(smem, Ah, Al, DDIM, Bh, Bl, DDIM, DDIM / 32, acc);

    const int lane = threadIdx.x & 31, wid = threadIdx.x >> 5;
    const int wm0 = (wid >> 2) * 64, wn0 = (wid & 3) * 32;
    float* C = g_S + (size_t)b * LSEQ * NJ;
    #pragma unroll
    for (int mt = 0; mt < 4; ++mt)
        #pragma unroll
        for (int nt = 0; nt < 4; ++nt)
            #pragma unroll
            for (int rh = 0; rh < 2; ++rh) {
                int m = m0 + wm0 + mt * 16 + (lane >> 2) + rh * 8;
                int n = n0 + wn0 + nt * 8 + (lane & 3) * 2;
                *(float2*)(C + (size_t)m * NJ + n) =
                    make_float2(acc[mt][nt][rh * 2], acc[mt][nt][rh * 2 + 1]);
            }
}

// ---------------------------------------------------------------------------
// Softmax + combined weights -> g_Chi / g_Clo
// ---------------------------------------------------------------------------
__global__ __launch_bounds__(256) void k_softmax(const float* __restrict__ qmask,
                                                 const float* __restrict__ kmask)
{
    const int row = blockIdx.x;
    const int b   = row >> 8;

    __shared__ float buf[NJ];
    __shared__ float qm[NJ];
    __shared__ float sim2[32];
    __shared__ float tvalid[32];
    __shared__ float wn[NTURN];

    const int tid = threadIdx.x;
    const float* srow = g_S + (size_t)row * NJ;
    const float* qmrow = qmask + b * NJ;

    for (int j = tid; j < NJ; j += 256) { buf[j] = srow[j]; qm[j] = qmrow[j]; }
    __syncthreads();

    const int wid = tid >> 5, lane = tid & 31;
    for (int n = wid; n < NTURN; n += 8) {
        const int base = n * JTOK;
        float q1 = qm[base + lane],  q2 = qm[base + 32 + lane];
        float s1 = buf[base + lane], s2 = buf[base + 32 + lane];
        float x1 = (q1 == 0.0f) ? NEGV : s1;
        float x2 = (q2 == 0.0f) ? NEGV : s2;
        float mx = fmaxf(x1, x2);
        #pragma unroll
        for (int o = 16; o; o >>= 1) mx = fmaxf(mx, __shfl_xor_sync(0xFFFFFFFFu, mx, o));
        float e1 = __expf(x1 - mx), e2 = __expf(x2 - mx);
        float es = e1 + e2, qs = q1 + q2, sp = e1 * s1 + e2 * s2;
        #pragma unroll
        for (int o = 16; o; o >>= 1) {
            es += __shfl_xor_sync(0xFFFFFFFFu, es, o);
            qs += __shfl_xor_sync(0xFFFFFFFFu, qs, o);
            sp += __shfl_xor_sync(0xFFFFFFFFu, sp, o);
        }
        float inv = 1.0f / es;
        buf[base + lane]      = e1 * inv;
        buf[base + 32 + lane] = e2 * inv;
        if (lane == 0) { sim2[n] = sp * inv; tvalid[n] = qs; }
    }
    __syncthreads();

    if (wid == 0) {
        float v = (lane < NTURN && tvalid[lane] != 0.0f) ? sim2[lane] : NEGV;
        float mx = v;
        #pragma unroll
        for (int o = 16; o; o >>= 1) mx = fmaxf(mx, __shfl_xor_sync(0xFFFFFFFFu, mx, o));
        float e = (lane < NTURN) ? __expf(v - mx) : 0.0f;
        float es = e;
        #pragma unroll
        for (int o = 16; o; o >>= 1) es += __shfl_xor_sync(0xFFFFFFFFu, es, o);
        if (lane < NTURN) wn[lane] = e / es;
    }
    __syncthreads();

    const float m = kmask[row];
    for (int idx = tid; idx < NJ; idx += 256) {
        const int n = idx >> 6;
        float c = m * wn[n] * buf[idx];
        __nv_bfloat16 h, l; split_bf(c, h, l);
        g_Chi[(size_t)row * NJ + idx] = h;
        g_Clo[(size_t)row * NJ + idx] = l;
    }
}

// ---------------------------------------------------------------------------
// GEMM2: attn[b] = C x queries (M=256, N=512, K=1280) -> g_Fhi/g_Flo
// ---------------------------------------------------------------------------
__global__ __launch_bounds__(256, 2) void k_hm2(const float* __restrict__ keys)
{
    extern __shared__ char smem[];
    const int b = blockIdx.z, m0 = blockIdx.y * 128, n0 = blockIdx.x * 128;
    const __nv_bfloat16* Ah = g_Chi  + ((size_t)b * LSEQ + m0) * NJ;
    const __nv_bfloat16* Al = g_Clo  + ((size_t)b * LSEQ + m0) * NJ;
    const __nv_bfloat16* Bh = g_Qthi + ((size_t)b * DDIM + n0) * NJ;
    const __nv_bfloat16* Bl = g_Qtlo + ((size_t)b * DDIM + n0) * NJ;
    float acc[4][4][4] = {};
    hmma_loop4(smem, Ah, Al, NJ, Bh, Bl, NJ, NJ / 32, acc);

    const int lane = threadIdx.x & 31, wid = threadIdx.x >> 5;
    const int wm0 = (wid >> 2) * 64, wn0 = (wid & 3) * 32;
    const float* keyb = keys + (size_t)b * LSEQ * DDIM;
    #pragma unroll
    for (int mt = 0; mt < 4; ++mt)
        #pragma unroll
        for (int nt = 0; nt < 4; ++nt)
            #pragma unroll
            for (int rh = 0; rh < 2; ++rh) {
                int m = m0 + wm0 + mt * 16 + (lane >> 2) + rh * 8;
                int n = n0 + wn0 + nt * 8 + (lane & 3) * 2;
                float a0 = acc[mt][nt][rh * 2], a1 = acc[mt][nt][rh * 2 + 1];
                float2 kv = *(const float2*)(keyb + (size_t)m * DDIM + n);
                float mu0 = a0 * kv.x, mu1 = a1 * kv.y;
                float df0 = a0 - kv.x, df1 = a1 - kv.y;
                float sq0 = df0 * df0, sq1 = df1 * df1;
                size_t rowo = ((size_t)b * LSEQ + m) * 1024;
                __nv_bfloat16 h0, l0, h1, l1;
                __nv_bfloat162 hp, lp;
                split_bf(mu0, h0, l0); split_bf(mu1, h1, l1);
                hp.x = h0; hp.y = h1; lp.x = l0; lp.y = l1;
                *(__nv_bfloat162*)(g_Fhi + rowo + n) = hp;
                *(__nv_bfloat162*)(g_Flo + rowo + n) = lp;
                split_bf(sq0, h0, l0); split_bf(sq1, h1, l1);
                hp.x = h0; hp.y = h1; lp.x = l0; lp.y = l1;
                *(__nv_bfloat162*)(g_Fhi + rowo + 512 + n) = hp;
                *(__nv_bfloat162*)(g_Flo + rowo + 512 + n) = lp;
            }
}

// ---------------------------------------------------------------------------
// GEMM3: out = relu(F x W^T + b)  (M=8192, N=512, K=1024)
// ---------------------------------------------------------------------------
__global__ __launch_bounds__(256, 2) void k_hm3(const float* __restrict__ bias,
                                                float* __restrict__ out)
{
    extern __shared__ char smem[];
    const int m0 = blockIdx.y * 128, n0 = blockIdx.x * 128;
    const __nv_bfloat16* Ah = g_Fhi + (size_t)m0 * 1024;
    const __nv_bfloat16* Al = g_Flo + (size_t)m0 * 1024;
    const __nv_bfloat16* Bh = g_Whi + (size_t)n0 * 1024;
    const __nv_bfloat16* Bl = g_Wlo + (size_t)n0 * 1024;
    float acc[4][4][4] = {};
    hmma_loop4(smem, Ah, Al, 1024, Bh, Bl, 1024, 1024 / 32, acc);

    const int lane = threadIdx.x & 31, wid = threadIdx.x >> 5;
    const int wm0 = (wid >> 2) * 64, wn0 = (wid & 3) * 32;
    #pragma unroll
    for (int mt = 0; mt < 4; ++mt)
        #pragma unroll
        for (int nt = 0; nt < 4; ++nt)
            #pragma unroll
            for (int rh = 0; rh < 2; ++rh) {
                int m = m0 + wm0 + mt * 16 + (lane >> 2) + rh * 8;
                int n = n0 + wn0 + nt * 8 + (lane & 3) * 2;
                float2 bb = *(const float2*)(bias + n);
                float v0 = fmaxf(acc[mt][nt][rh * 2]     + bb.x, 0.0f);
                float v1 = fmaxf(acc[mt][nt][rh * 2 + 1] + bb.y, 0.0f);
                *(float2*)(out + (size_t)m * DDIM + n) = make_float2(v0, v1);
            }
}

// ---------------------------------------------------------------------------
extern "C" void kernel_launch(void* const* d_in, const int* in_sizes, int n_in,
                              void* d_out, int out_size)
{
    const float* queries = (const float*)d_in[0];  // [32,20,64,512]
    const float* keys    = (const float*)d_in[1];  // [32,256,512]
    const float* qmask   = (const float*)d_in[2];  // [32,20,64]
    const float* kmask   = (const float*)d_in[3];  // [32,256]
    const float* Wm      = (const float*)d_in[4];  // [512,1024]
    const float* bias    = (const float*)d_in[5];  // [512]
    float* out = (float*)d_out;                    // [32,256,512]

    cudaFuncSetAttribute(k_hm1, cudaFuncAttributeMaxDynamicSharedMemorySize, SMEM_BYTES);
    cudaFuncSetAttribute(k_hm2, cudaFuncAttributeMaxDynamicSharedMemorySize, SMEM_BYTES);
    cudaFuncSetAttribute(k_hm3, cudaFuncAttributeMaxDynamicSharedMemorySize, SMEM_BYTES);

    conv_keys<<<4096, 256>>>(keys);
    conv_qt  <<<dim3(NJ / 64, DDIM / 32, BATCH), 256>>>(queries);
    conv_w   <<<512, 256>>>(Wm);

    k_hm1<<<dim3(NJ / 128, LSEQ / 128, BATCH), 256, SMEM_BYTES>>>();
    k_softmax<<<MROWS, 256>>>(qmask, kmask);
    k_hm2<<<dim3(DDIM / 128, LSEQ / 128, BATCH), 256, SMEM_BYTES>>>(keys);
    k_hm3<<<dim3(DDIM / 128, MROWS / 128, 1), 256, SMEM_BYTES>>>(bias, out);
}

// round 11
// speedup vs baseline: 1.8443x; 1.0085x over previous
#include <cuda_runtime.h>
#include <cuda_bf16.h>
#include <stdint.h>
#include <math.h>

// Shapes
#define BATCH 32
#define NTURN 20
#define JTOK  64
#define LSEQ  256
#define DDIM  512
#define NJ    1280
#define MROWS 8192
#define NEGV  (-4294967295.0f)

// Compact split scratch (hi/lo)
__device__ __align__(16) __nv_bfloat16 g_Khi [(size_t)BATCH*LSEQ*DDIM];
__device__ __align__(16) __nv_bfloat16 g_Klo [(size_t)BATCH*LSEQ*DDIM];
__device__ __align__(16) __nv_bfloat16 g_Qhi [(size_t)BATCH*NJ*DDIM];
__device__ __align__(16) __nv_bfloat16 g_Qlo [(size_t)BATCH*NJ*DDIM];
__device__ __align__(16) __nv_bfloat16 g_Qthi[(size_t)BATCH*DDIM*NJ];   // transposed [b][d][j]
__device__ __align__(16) __nv_bfloat16 g_Qtlo[(size_t)BATCH*DDIM*NJ];
__device__ __align__(16) float         g_S   [(size_t)BATCH*LSEQ*NJ];
__device__ __align__(16) __nv_bfloat16 g_Chi [(size_t)BATCH*LSEQ*NJ];
__device__ __align__(16) __nv_bfloat16 g_Clo [(size_t)BATCH*LSEQ*NJ];
__device__ __align__(16) __nv_bfloat16 g_Fhi [(size_t)MROWS*1024];
__device__ __align__(16) __nv_bfloat16 g_Flo [(size_t)MROWS*1024];
__device__ __align__(16) __nv_bfloat16 g_Whi [(size_t)DDIM*1024];
__device__ __align__(16) __nv_bfloat16 g_Wlo [(size_t)DDIM*1024];

// ---------------------------------------------------------------------------
// helpers
// ---------------------------------------------------------------------------
__device__ __forceinline__ uint32_t smem_u32(const void* p) {
    uint32_t a;
    asm("{ .reg .u64 t; cvta.to.shared.u64 t, %1; cvt.u32.u64 %0, t; }" : "=r"(a) : "l"(p));
    return a;
}
__device__ __forceinline__ void split_bf(float x, __nv_bfloat16& h, __nv_bfloat16& l) {
    h = __float2bfloat16(x);
    l = __float2bfloat16(x - __bfloat162float(h));
}
__device__ __forceinline__ void cpa16(uint32_t saddr, const void* g) {
    asm volatile("cp.async.cg.shared.global [%0], [%1], 16;" :: "r"(saddr), "l"(g));
}
#define CP_COMMIT() asm volatile("cp.async.commit_group;")
#define CP_WAIT0()  asm volatile("cp.async.wait_group 0;")

#define LDSM4(R, ADDR) \
    asm volatile("ldmatrix.sync.aligned.m8n8.x4.shared.b16 {%0,%1,%2,%3}, [%4];" \
        : "=r"((R)[0]), "=r"((R)[1]), "=r"((R)[2]), "=r"((R)[3]) : "r"(ADDR))

#define MMA16816(C, A, B0, B1) \
    asm volatile("mma.sync.aligned.m16n8k16.row.col.f32.bf16.bf16.f32 " \
        "{%0,%1,%2,%3},{%4,%5,%6,%7},{%8,%9},{%0,%1,%2,%3};" \
        : "+f"((C)[0]), "+f"((C)[1]), "+f"((C)[2]), "+f"((C)[3]) \
        : "r"((A)[0]), "r"((A)[1]), "r"((A)[2]), "r"((A)[3]), "r"(B0), "r"(B1))

// smem: 2 stages x 4 tiles (A_hi, A_lo, B_hi, B_lo); tile = 128 rows x 32 K-cols
#define PITCH 40
#define TILE  (128 * PITCH * 2)           // 10240 B
#define STG   (4 * TILE)                  // 40960 B per stage
#define SMEM_BYTES (2 * STG)              // 81920 B (2 CTAs/SM = 160KB)

// ---------------------------------------------------------------------------
// load one K=32 chunk: 4 tiles (A_hi, A_lo, B_hi, B_lo)
// ---------------------------------------------------------------------------
__device__ __forceinline__ void load_tiles4(uint32_t sb, int stage,
                                            const __nv_bfloat16* Ah, const __nv_bfloat16* Al, int lda,
                                            const __nv_bfloat16* Bh, const __nv_bfloat16* Bl, int ldb,
                                            int koff)
{
    const int tid = threadIdx.x;
    const uint32_t s0 = sb + stage * STG;
    #pragma unroll
    for (int i = 0; i < 2; ++i) {
        int id = tid + i * 256;
        int r = id >> 2, cc = id & 3;
        uint32_t so = (uint32_t)(r * PITCH + cc * 8) * 2;
        size_t goA = (size_t)r * lda + koff + cc * 8;
        size_t goB = (size_t)r * ldb + koff + cc * 8;
        cpa16(s0 + so,            Ah + goA);
        cpa16(s0 + TILE + so,     Al + goA);
        cpa16(s0 + 2 * TILE + so, Bh + goB);
        cpa16(s0 + 3 * TILE + so, Bl + goB);
    }
}

// per K=32 chunk: 2 k16 steps; per mt: load a_hi/a_lo frags, then issue the
// three products in separate nt-sweeps so same-accumulator MMAs are 4 apart.
__device__ __forceinline__ void hmma_compute4(uint32_t sb, int stage,
                                              int lane, int wm0, int wn0,
                                              float acc[4][4][4])
{
    const uint32_t sAh = sb + stage * STG;
    const uint32_t sAl = sAh + TILE;
    const uint32_t sBh = sAh + 2 * TILE;
    const uint32_t sBl = sAh + 3 * TILE;
    const int rowoff = lane & 15;
    #pragma unroll
    for (int ks = 0; ks < 2; ++ks) {
        const int coloff = ks * 16 + (lane >> 4) * 8;
        uint32_t bh[2][4], blo[2][4];
        #pragma unroll
        for (int np = 0; np < 2; ++np) {
            uint32_t bo = (uint32_t)((wn0 + np * 16 + rowoff) * PITCH + coloff) * 2;
            LDSM4(bh[np],  sBh + bo);
            LDSM4(blo[np], sBl + bo);
        }
        #pragma unroll
        for (int mt = 0; mt < 4; ++mt) {
            uint32_t ah[4], al[4];
            uint32_t ao = (uint32_t)((wm0 + mt * 16 + rowoff) * PITCH + coloff) * 2;
            LDSM4(ah, sAh + ao);
            LDSM4(al, sAl + ao);
            #pragma unroll
            for (int nt = 0; nt < 4; ++nt)
                MMA16816(acc[mt][nt], ah, bh[nt >> 1][nt & 1],  bh[nt >> 1][2 + (nt & 1)]);
            #pragma unroll
            for (int nt = 0; nt < 4; ++nt)
                MMA16816(acc[mt][nt], ah, blo[nt >> 1][nt & 1], blo[nt >> 1][2 + (nt & 1)]);
            #pragma unroll
            for (int nt = 0; nt < 4; ++nt)
                MMA16816(acc[mt][nt], al, bh[nt >> 1][nt & 1],  bh[nt >> 1][2 + (nt & 1)]);
        }
    }
}

// 2-stage pipelined mainloop over bl K=32 chunks; one __syncthreads per chunk.
__device__ __forceinline__ void hmma_loop4(char* smem,
                                           const __nv_bfloat16* Ahi, const __nv_bfloat16* Alo, int lda,
                                           const __nv_bfloat16* Bhi, const __nv_bfloat16* Blo, int ldb,
                                           int bl, float acc[4][4][4])
{
    const int tid = threadIdx.x;
    const int lane = tid & 31, wid = tid >> 5;
    const int wm0 = (wid >> 2) * 64, wn0 = (wid & 3) * 32;
    const uint32_t sb = smem_u32(smem);

    load_tiles4(sb, 0, Ahi, Alo, lda, Bhi, Blo, ldb, 0);
    CP_COMMIT();

    for (int c = 0; c < bl; ++c) {
        CP_WAIT0();
        __syncthreads();
        if (c + 1 < bl) {
            load_tiles4(sb, (c + 1) & 1, Ahi, Alo, lda, Bhi, Blo, ldb, (c + 1) * 32);
            CP_COMMIT();
        }
        hmma_compute4(sb, c & 1, lane, wm0, wn0, acc);
    }
}

// ---------------------------------------------------------------------------
// Conversion kernels (fp32 -> compact hi/lo bf16)
// ---------------------------------------------------------------------------
__device__ __forceinline__ void split4_store(const float4 v, __nv_bfloat16* hi, __nv_bfloat16* lo, size_t o)
{
    __nv_bfloat16 h[4], l[4];
    split_bf(v.x, h[0], l[0]); split_bf(v.y, h[1], l[1]);
    split_bf(v.z, h[2], l[2]); split_bf(v.w, h[3], l[3]);
    __nv_bfloat162 hh0, hh1, ll0, ll1;
    hh0.x = h[0]; hh0.y = h[1]; hh1.x = h[2]; hh1.y = h[3];
    ll0.x = l[0]; ll0.y = l[1]; ll1.x = l[2]; ll1.y = l[3];
    *(__nv_bfloat162*)(hi + o) = hh0; *(__nv_bfloat162*)(hi + o + 2) = hh1;
    *(__nv_bfloat162*)(lo + o) = ll0; *(__nv_bfloat162*)(lo + o + 2) = ll1;
}

__global__ __launch_bounds__(256) void conv_keys(const float* __restrict__ keys)
{
    size_t t = (size_t)blockIdx.x * 256 + threadIdx.x;
    size_t o = t * 4;
    split4_store(*(const float4*)(keys + o), g_Khi, g_Klo, o);
}
__global__ __launch_bounds__(256) void conv_w(const float* __restrict__ Wm)
{
    size_t t = (size_t)blockIdx.x * 256 + threadIdx.x;
    size_t o = t * 4;
    split4_store(*(const float4*)(Wm + o), g_Whi, g_Wlo, o);
}

// Merged split + transpose: q[b][j][d] -> Q{hi,lo}[b][j][d] AND Qt{hi,lo}[b][d][j].
__global__ __launch_bounds__(256) void conv_qt(const float* __restrict__ q)
{
    __shared__ __nv_bfloat16 shh[32][72];
    __shared__ __nv_bfloat16 shl[32][72];
    const int b  = blockIdx.z;
    const int d0 = blockIdx.y * 32;
    const int j0 = blockIdx.x * 64;
    const int t  = threadIdx.x;

    #pragma unroll
    for (int i = 0; i < 2; ++i) {
        int jj = (t >> 3) + i * 32;               // 0..63
        int dd = (t & 7) * 4;                     // 0..28
        size_t qo = ((size_t)b * NJ + j0 + jj) * DDIM + d0 + dd;
        float4 v = *(const float4*)(q + qo);
        __nv_bfloat16 h0, l0, h1, l1, h2, l2, h3, l3;
        split_bf(v.x, h0, l0); split_bf(v.y, h1, l1);
        split_bf(v.z, h2, l2); split_bf(v.w, h3, l3);
        __nv_bfloat162 hp0, hp1, lp0, lp1;
        hp0.x = h0; hp0.y = h1; hp1.x = h2; hp1.y = h3;
        lp0.x = l0; lp0.y = l1; lp1.x = l2; lp1.y = l3;
        *(__nv_bfloat162*)(g_Qhi + qo)     = hp0; *(__nv_bfloat162*)(g_Qhi + qo + 2) = hp1;
        *(__nv_bfloat162*)(g_Qlo + qo)     = lp0; *(__nv_bfloat162*)(g_Qlo + qo + 2) = lp1;
        shh[dd+0][jj] = h0; shl[dd+0][jj] = l0;
        shh[dd+1][jj] = h1; shl[dd+1][jj] = l1;
        shh[dd+2][jj] = h2; shl[dd+2][jj] = l2;
        shh[dd+3][jj] = h3; shl[dd+3][jj] = l3;
    }
    __syncthreads();

    const int r  = t >> 3;                        // 0..31 (d row)
    const int pc = t & 7;                         // 8 bf16 = 16B chunk
    size_t o = ((size_t)b * DDIM + d0 + r) * NJ + j0 + pc * 8;
    *(uint4*)(g_Qthi + o) = *(const uint4*)&shh[r][pc * 8];
    *(uint4*)(g_Qtlo + o) = *(const uint4*)&shl[r][pc * 8];
}

// ---------------------------------------------------------------------------
// GEMM1: scores[b] = keys x queries^T  (M=256, N=1280, K=512) -> g_S
// ---------------------------------------------------------------------------
__global__ __launch_bounds__(256, 2) void k_hm1()
{
    extern __shared__ char smem[];
    const int b = blockIdx.z, m0 = blockIdx.y * 128, n0 = blockIdx.x * 128;
    const __nv_bfloat16* Ah = g_Khi + ((size_t)b * LSEQ + m0) * DDIM;
    const __nv_bfloat16* Al = g_Klo + ((size_t)b * LSEQ + m0) * DDIM;
    const __nv_bfloat16* Bh = g_Qhi + ((size_t)b * NJ + n0) * DDIM;
    const __nv_bfloat16* Bl = g_Qlo + ((size_t)b * NJ + n0) * DDIM;
    float acc[4][4][4] = {};
    hmma_loop4(smem, Ah, Al, DDIM, Bh, Bl, DDIM, DDIM / 32, acc);

    const int lane = threadIdx.x & 31, wid = threadIdx.x >> 5;
    const int wm0 = (wid >> 2) * 64, wn0 = (wid & 3) * 32;
    float* C = g_S + (size_t)b * LSEQ * NJ;
    #pragma unroll
    for (int mt = 0; mt < 4; ++mt)
        #pragma unroll
        for (int nt = 0; nt < 4; ++nt)
            #pragma unroll
            for (int rh = 0; rh < 2; ++rh) {
                int m = m0 + wm0 + mt * 16 + (lane >> 2) + rh * 8;
                int n = n0 + wn0 + nt * 8 + (lane & 3) * 2;
                *(float2*)(C + (size_t)m * NJ + n) =
                    make_float2(acc[mt][nt][rh * 2], acc[mt][nt][rh * 2 + 1]);
            }
}

// ---------------------------------------------------------------------------
// Softmax + combined weights -> g_Chi / g_Clo
// ---------------------------------------------------------------------------
__global__ __launch_bounds__(256) void k_softmax(const float* __restrict__ qmask,
                                                 const float* __restrict__ kmask)
{
    const int row = blockIdx.x;
    const int b   = row >> 8;

    __shared__ float buf[NJ];
    __shared__ float qm[NJ];
    __shared__ float sim2[32];
    __shared__ float tvalid[32];
    __shared__ float wn[NTURN];

    const int tid = threadIdx.x;
    const float* srow = g_S + (size_t)row * NJ;
    const float* qmrow = qmask + b * NJ;

    for (int j = tid; j < NJ; j += 256) { buf[j] = srow[j]; qm[j] = qmrow[j]; }
    __syncthreads();

    const int wid = tid >> 5, lane = tid & 31;
    for (int n = wid; n < NTURN; n += 8) {
        const int base = n * JTOK;
        float q1 = qm[base + lane],  q2 = qm[base + 32 + lane];
        float s1 = buf[base + lane], s2 = buf[base + 32 + lane];
        float x1 = (q1 == 0.0f) ? NEGV : s1;
        float x2 = (q2 == 0.0f) ? NEGV : s2;
        float mx = fmaxf(x1, x2);
        #pragma unroll
        for (int o = 16; o; o >>= 1) mx = fmaxf(mx, __shfl_xor_sync(0xFFFFFFFFu, mx, o));
        float e1 = __expf(x1 - mx), e2 = __expf(x2 - mx);
        float es = e1 + e2, qs = q1 + q2, sp = e1 * s1 + e2 * s2;
        #pragma unroll
        for (int o = 16; o; o >>= 1) {
            es += __shfl_xor_sync(0xFFFFFFFFu, es, o);
            qs += __shfl_xor_sync(0xFFFFFFFFu, qs, o);
            sp += __shfl_xor_sync(0xFFFFFFFFu, sp, o);
        }
        float inv = 1.0f / es;
        buf[base + lane]      = e1 * inv;
        buf[base + 32 + lane] = e2 * inv;
        if (lane == 0) { sim2[n] = sp * inv; tvalid[n] = qs; }
    }
    __syncthreads();

    if (wid == 0) {
        float v = (lane < NTURN && tvalid[lane] != 0.0f) ? sim2[lane] : NEGV;
        float mx = v;
        #pragma unroll
        for (int o = 16; o; o >>= 1) mx = fmaxf(mx, __shfl_xor_sync(0xFFFFFFFFu, mx, o));
        float e = (lane < NTURN) ? __expf(v - mx) : 0.0f;
        float es = e;
        #pragma unroll
        for (int o = 16; o; o >>= 1) es += __shfl_xor_sync(0xFFFFFFFFu, es, o);
        if (lane < NTURN) wn[lane] = e / es;
    }
    __syncthreads();

    const float m = kmask[row];
    for (int idx = tid; idx < NJ; idx += 256) {
        const int n = idx >> 6;
        float c = m * wn[n] * buf[idx];
        __nv_bfloat16 h, l; split_bf(c, h, l);
        g_Chi[(size_t)row * NJ + idx] = h;
        g_Clo[(size_t)row * NJ + idx] = l;
    }
}

// ---------------------------------------------------------------------------
// GEMM2: attn[b] = C x queries (M=256, N=512, K=1280) -> g_Fhi/g_Flo
// ---------------------------------------------------------------------------
__global__ __launch_bounds__(256, 2) void k_hm2(const float* __restrict__ keys)
{
    extern __shared__ char smem[];
    const int b = blockIdx.z, m0 = blockIdx.y * 128, n0 = blockIdx.x * 128;
    const __nv_bfloat16* Ah = g_Chi  + ((size_t)b * LSEQ + m0) * NJ;
    const __nv_bfloat16* Al = g_Clo  + ((size_t)b * LSEQ + m0) * NJ;
    const __nv_bfloat16* Bh = g_Qthi + ((size_t)b * DDIM + n0) * NJ;
    const __nv_bfloat16* Bl = g_Qtlo + ((size_t)b * DDIM + n0) * NJ;
    float acc[4][4][4] = {};
    hmma_loop4(smem, Ah, Al, NJ, Bh, Bl, NJ, NJ / 32, acc);

    const int lane = threadIdx.x & 31, wid = threadIdx.x >> 5;
    const int wm0 = (wid >> 2) * 64, wn0 = (wid & 3) * 32;
    const float* keyb = keys + (size_t)b * LSEQ * DDIM;
    #pragma unroll
    for (int mt = 0; mt < 4; ++mt)
        #pragma unroll
        for (int nt = 0; nt < 4; ++nt)
            #pragma unroll
            for (int rh = 0; rh < 2; ++rh) {
                int m = m0 + wm0 + mt * 16 + (lane >> 2) + rh * 8;
                int n = n0 + wn0 + nt * 8 + (lane & 3) * 2;
                float a0 = acc[mt][nt][rh * 2], a1 = acc[mt][nt][rh * 2 + 1];
                float2 kv = *(const float2*)(keyb + (size_t)m * DDIM + n);
                float mu0 = a0 * kv.x, mu1 = a1 * kv.y;
                float df0 = a0 - kv.x, df1 = a1 - kv.y;
                float sq0 = df0 * df0, sq1 = df1 * df1;
                size_t rowo = ((size_t)b * LSEQ + m) * 1024;
                __nv_bfloat16 h0, l0, h1, l1;
                __nv_bfloat162 hp, lp;
                split_bf(mu0, h0, l0); split_bf(mu1, h1, l1);
                hp.x = h0; hp.y = h1; lp.x = l0; lp.y = l1;
                *(__nv_bfloat162*)(g_Fhi + rowo + n) = hp;
                *(__nv_bfloat162*)(g_Flo + rowo + n) = lp;
                split_bf(sq0, h0, l0); split_bf(sq1, h1, l1);
                hp.x = h0; hp.y = h1; lp.x = l0; lp.y = l1;
                *(__nv_bfloat162*)(g_Fhi + rowo + 512 + n) = hp;
                *(__nv_bfloat162*)(g_Flo + rowo + 512 + n) = lp;
            }
}

// ---------------------------------------------------------------------------
// GEMM3: out = relu(F x W^T + b)  (M=8192, N=512, K=1024)
// ---------------------------------------------------------------------------
__global__ __launch_bounds__(256, 2) void k_hm3(const float* __restrict__ bias,
                                                float* __restrict__ out)
{
    extern __shared__ char smem[];
    const int m0 = blockIdx.y * 128, n0 = blockIdx.x * 128;
    const __nv_bfloat16* Ah = g_Fhi + (size_t)m0 * 1024;
    const __nv_bfloat16* Al = g_Flo + (size_t)m0 * 1024;
    const __nv_bfloat16* Bh = g_Whi + (size_t)n0 * 1024;
    const __nv_bfloat16* Bl = g_Wlo + (size_t)n0 * 1024;
    float acc[4][4][4] = {};
    hmma_loop4(smem, Ah, Al, 1024, Bh, Bl, 1024, 1024 / 32, acc);

    const int lane = threadIdx.x & 31, wid = threadIdx.x >> 5;
    const int wm0 = (wid >> 2) * 64, wn0 = (wid & 3) * 32;
    #pragma unroll
    for (int mt = 0; mt < 4; ++mt)
        #pragma unroll
        for (int nt = 0; nt < 4; ++nt)
            #pragma unroll
            for (int rh = 0; rh < 2; ++rh) {
                int m = m0 + wm0 + mt * 16 + (lane >> 2) + rh * 8;
                int n = n0 + wn0 + nt * 8 + (lane & 3) * 2;
                float2 bb = *(const float2*)(bias + n);
                float v0 = fmaxf(acc[mt][nt][rh * 2]     + bb.x, 0.0f);
                float v1 = fmaxf(acc[mt][nt][rh * 2 + 1] + bb.y, 0.0f);
                *(float2*)(out + (size_t)m * DDIM + n) = make_float2(v0, v1);
            }
}

// ---------------------------------------------------------------------------
extern "C" void kernel_launch(void* const* d_in, const int* in_sizes, int n_in,
                              void* d_out, int out_size)
{
    const float* queries = (const float*)d_in[0];  // [32,20,64,512]
    const float* keys    = (const float*)d_in[1];  // [32,256,512]
    const float* qmask   = (const float*)d_in[2];  // [32,20,64]
    const float* kmask   = (const float*)d_in[3];  // [32,256]
    const float* Wm      = (const float*)d_in[4];  // [512,1024]
    const float* bias    = (const float*)d_in[5];  // [512]
    float* out = (float*)d_out;                    // [32,256,512]

    cudaFuncSetAttribute(k_hm1, cudaFuncAttributeMaxDynamicSharedMemorySize, SMEM_BYTES);
    cudaFuncSetAttribute(k_hm2, cudaFuncAttributeMaxDynamicSharedMemorySize, SMEM_BYTES);
    cudaFuncSetAttribute(k_hm3, cudaFuncAttributeMaxDynamicSharedMemorySize, SMEM_BYTES);

    conv_keys<<<4096, 256>>>(keys);
    conv_qt  <<<dim3(NJ / 64, DDIM / 32, BATCH), 256>>>(queries);
    conv_w   <<<512, 256>>>(Wm);

    k_hm1<<<dim3(NJ / 128, LSEQ / 128, BATCH), 256, SMEM_BYTES>>>();
    k_softmax<<<MROWS, 256>>>(qmask, kmask);
    k_hm2<<<dim3(DDIM / 128, LSEQ / 128, BATCH), 256, SMEM_BYTES>>>(keys);
    k_hm3<<<dim3(DDIM / 128, MROWS / 128, 1), 256, SMEM_BYTES>>>(bias, out);
}